// round 11
// baseline (speedup 1.0000x reference)
#include <cuda_runtime.h>
#include <cuda_bf16.h>
#include <cstdint>

#define Bb 32
#define Ll 1024
#define LMD 1024
#define Dd 128
#define Rr 3
#define NLAYERS 2
#define Cc 8
#define Nn (Bb*Ll)          // 32768
#define Ee 524288
#define NRr (Nn*Rr)         // 98304

typedef __nv_bfloat16 bf16;

// ---------------- scratch (device globals; no allocations allowed) ----------
__device__ float g_lm[Nn*Dd];         // post-LN lm features (f32, for cls + agg)
__device__ bf16  g_lmh[Nn*Dd], g_lml[Nn*Dd];
__device__ float g_x[Nn*Dd];          // layer-0 output f32 (for agg gather)
__device__ bf16  g_xh[Nn*Dd], g_xl[Nn*Dd];
__device__ float g_x2[Nn*Dd];         // pre-LN temp / layer-1 output
__device__ bf16  g_aggh[(size_t)Nn*Rr*Dd], g_aggl[(size_t)Nn*Rr*Dd];
__device__ bf16  g_Wth[LMD*Dd], g_Wtl[LMD*Dd];                 // lm_W^T split
__device__ bf16  g_Wrelh[NLAYERS*Rr*Dd*Dd], g_Wrell[NLAYERS*Rr*Dd*Dd];
__device__ bf16  g_Wrooth[NLAYERS*Dd*Dd], g_Wrootl[NLAYERS*Dd*Dd];
__device__ float g_logits_scratch[Nn*Cc];
__device__ int   g_cnt[NRr];
__device__ int   g_cursor[NRr];
__device__ int   g_off[NRr+1];
__device__ int   g_bsum[128];
__device__ int   g_srcs[Ee];
__device__ float g_loss[2];
__device__ int   g_is64;

// ---------------- small helpers ----------------
__device__ __forceinline__ uint32_t sptr(const void* p) {
    return (uint32_t)__cvta_generic_to_shared(p);
}
__device__ __forceinline__ void bfsplit(float v, bf16& h, bf16& l) {
    h = __float2bfloat16(v);
    l = __float2bfloat16(v - __bfloat162float(h));
}

__device__ __forceinline__ void ldsm4(uint32_t& r0, uint32_t& r1, uint32_t& r2, uint32_t& r3,
                                      uint32_t addr) {
    asm volatile("ldmatrix.sync.aligned.m8n8.x4.shared.b16 {%0,%1,%2,%3}, [%4];"
                 : "=r"(r0), "=r"(r1), "=r"(r2), "=r"(r3) : "r"(addr));
}
__device__ __forceinline__ void ldsm4t(uint32_t& r0, uint32_t& r1, uint32_t& r2, uint32_t& r3,
                                       uint32_t addr) {
    asm volatile("ldmatrix.sync.aligned.m8n8.x4.trans.shared.b16 {%0,%1,%2,%3}, [%4];"
                 : "=r"(r0), "=r"(r1), "=r"(r2), "=r"(r3) : "r"(addr));
}
__device__ __forceinline__ void mma16816(float* c, const uint32_t* a, uint32_t b0, uint32_t b1) {
    asm volatile("mma.sync.aligned.m16n8k16.row.col.f32.bf16.bf16.f32 "
                 "{%0,%1,%2,%3},{%4,%5,%6,%7},{%8,%9},{%0,%1,%2,%3};"
                 : "+f"(c[0]), "+f"(c[1]), "+f"(c[2]), "+f"(c[3])
                 : "r"(a[0]), "r"(a[1]), "r"(a[2]), "r"(a[3]), "r"(b0), "r"(b1));
}

// ---------------- int dtype probe ----------------
__global__ void probe_k(const int* __restrict__ p) {
    __shared__ int bad;
    if (threadIdx.x == 0) bad = 0;
    __syncthreads();
    for (int i = threadIdx.x; i < 1024; i += blockDim.x)
        if (p[2*i + 1] != 0) bad = 1;
    __syncthreads();
    if (threadIdx.x == 0) g_is64 = bad ? 0 : 1;
}
__device__ __forceinline__ int load_int(const void* p, long long idx) {
    if (g_is64) return (int)((const long long*)p)[idx];
    return ((const int*)p)[idx];
}

// ---------------- utility kernels ----------------
__global__ void zero_k() {
    int i = blockIdx.x*blockDim.x + threadIdx.x;
    int stride = gridDim.x*blockDim.x;
    for (; i < NRr; i += stride) { g_cnt[i] = 0; g_cursor[i] = 0; }
    if (blockIdx.x == 0 && threadIdx.x < 2) g_loss[threadIdx.x] = 0.f;
}

// lm_W [128][1024] -> Wt [1024][128], split into bf16 hi/lo. Output-indexed.
__global__ void transWsplit_k(const float* __restrict__ W) {
    int o = blockIdx.x*blockDim.x + threadIdx.x;     // 131072
    if (o >= LMD*Dd) return;
    int k = o >> 7, h = o & 127;
    float v = W[h*LMD + k];
    bf16 hi, lo; bfsplit(v, hi, lo);
    g_Wth[o] = hi; g_Wtl[o] = lo;
}

__global__ void splitW_k(const float* __restrict__ src, int n, bf16* __restrict__ h, bf16* __restrict__ l) {
    int i = blockIdx.x*blockDim.x + threadIdx.x;
    int stride = gridDim.x*blockDim.x;
    for (; i < n; i += stride) {
        bf16 hi, lo; bfsplit(src[i], hi, lo);
        h[i] = hi; l[i] = lo;
    }
}

// ---------------- tensor-core GEMM with 3xBF16 split, single pass ------------
// C[M x 128] = relu( sum_parts (Ah@Bh + Ah@Bl + Al@Bh) + bias )
// A source per part: either f32 (split on load into smem) or pre-split bf16 pair.
// Block 128x128, BK=32, 256 threads = 8 warps (2 m x 4 n), warp tile 64x32.
__global__ __launch_bounds__(256, 2)
void gemm3_k(const float* __restrict__ A1f,
             const bf16* __restrict__ A1h, const bf16* __restrict__ A1l, int K1,
             const bf16* __restrict__ B1h, const bf16* __restrict__ B1l,
             const bf16* __restrict__ A2h, const bf16* __restrict__ A2l, int K2,
             const bf16* __restrict__ B2h, const bf16* __restrict__ B2l,
             const float* __restrict__ bias, float* __restrict__ C,
             bf16* __restrict__ Ch, bf16* __restrict__ Cl)
{
    __shared__ bf16 Ash[128][40];       // pad 8 -> row stride 80B
    __shared__ bf16 Asl[128][40];
    __shared__ bf16 Bsh[32][136];       // pad 8 -> row stride 272B
    __shared__ bf16 Bsl[32][136];

    const int tid  = threadIdx.x;
    const int wid  = tid >> 5;
    const int lane = tid & 31;
    const int wm   = wid >> 2;          // 0..1 -> m offset *64
    const int wn   = wid & 3;           // 0..3 -> n offset *32
    const int m0   = blockIdx.x * 128;
    const int g    = lane >> 2;
    const int q    = lane & 3;

    float acc[4][4][4];
#pragma unroll
    for (int i = 0; i < 4; i++)
#pragma unroll
        for (int j = 0; j < 4; j++)
#pragma unroll
            for (int r = 0; r < 4; r++) acc[i][j][r] = 0.f;

#pragma unroll 1
    for (int part = 0; part < 2; part++) {
        const float* Af = part ? nullptr : A1f;
        const bf16* Ah  = part ? A2h : A1h;
        const bf16* Al  = part ? A2l : A1l;
        const bf16* Bh  = part ? B2h : B1h;
        const bf16* Bl  = part ? B2l : B1l;
        const int K     = part ? K2  : K1;
        if (K == 0 || (Af == nullptr && Ah == nullptr)) continue;

#pragma unroll 1
        for (int kt = 0; kt < K; kt += 32) {
            // ---- load A tile 128x32 into Ash/Asl ----
            if (Af) {
                // f32 source: 4096 floats = 1024 float4, 4 iters
                int c = tid;
#pragma unroll
                for (int it = 0; it < 4; it++, c += 256) {
                    int row = c >> 3, cc = c & 7;            // cc*4 = col
                    float4 v = *(const float4*)(Af + (size_t)(m0 + row) * K + kt + cc*4);
                    bf16 h0,h1,h2,h3,l0,l1,l2,l3;
                    bfsplit(v.x,h0,l0); bfsplit(v.y,h1,l1);
                    bfsplit(v.z,h2,l2); bfsplit(v.w,h3,l3);
                    __nv_bfloat162 hh0 = __halves2bfloat162(h0,h1);
                    __nv_bfloat162 hh1 = __halves2bfloat162(h2,h3);
                    __nv_bfloat162 ll0 = __halves2bfloat162(l0,l1);
                    __nv_bfloat162 ll1 = __halves2bfloat162(l2,l3);
                    *(__nv_bfloat162*)&Ash[row][cc*4]     = hh0;
                    *(__nv_bfloat162*)&Ash[row][cc*4 + 2] = hh1;
                    *(__nv_bfloat162*)&Asl[row][cc*4]     = ll0;
                    *(__nv_bfloat162*)&Asl[row][cc*4 + 2] = ll1;
                }
            } else {
                // pre-split bf16: 512 uint4 per matrix, 2 iters each
                int c = tid;
#pragma unroll
                for (int it = 0; it < 2; it++, c += 256) {
                    int row = c >> 2, cc = c & 3;            // cc*8 = col
                    *(uint4*)&Ash[row][cc*8] = *(const uint4*)(Ah + (size_t)(m0 + row) * K + kt + cc*8);
                    *(uint4*)&Asl[row][cc*8] = *(const uint4*)(Al + (size_t)(m0 + row) * K + kt + cc*8);
                }
            }
            // ---- load B tiles 32x128 ----
            {
                int c = tid;
#pragma unroll
                for (int it = 0; it < 2; it++, c += 256) {
                    int row = c >> 4, cc = c & 15;
                    *(uint4*)&Bsh[row][cc*8] = *(const uint4*)(Bh + (size_t)(kt + row) * 128 + cc*8);
                    *(uint4*)&Bsl[row][cc*8] = *(const uint4*)(Bl + (size_t)(kt + row) * 128 + cc*8);
                }
            }
            __syncthreads();

#pragma unroll
            for (int ks = 0; ks < 32; ks += 16) {
                uint32_t af[4][4];
                // A-hi fragments
#pragma unroll
                for (int f = 0; f < 4; f++)
                    ldsm4(af[f][0], af[f][1], af[f][2], af[f][3],
                          sptr(&Ash[wm*64 + 16*f + (lane & 15)][ks + ((lane >> 4) << 3)]));
                uint32_t bh[2][4], bl[2][4];
#pragma unroll
                for (int t = 0; t < 2; t++) {
                    ldsm4t(bh[t][0], bh[t][1], bh[t][2], bh[t][3],
                           sptr(&Bsh[ks + (lane & 15)][wn*32 + 16*t + ((lane >> 4) << 3)]));
                    ldsm4t(bl[t][0], bl[t][1], bl[t][2], bl[t][3],
                           sptr(&Bsl[ks + (lane & 15)][wn*32 + 16*t + ((lane >> 4) << 3)]));
                }
                // Ah x Bh, Ah x Bl
#pragma unroll
                for (int mf = 0; mf < 4; mf++)
#pragma unroll
                    for (int nf = 0; nf < 4; nf++) {
                        mma16816(acc[mf][nf], af[mf], bh[nf>>1][(nf&1)*2], bh[nf>>1][(nf&1)*2+1]);
                        mma16816(acc[mf][nf], af[mf], bl[nf>>1][(nf&1)*2], bl[nf>>1][(nf&1)*2+1]);
                    }
                // reload af with A-lo (reuses registers), Al x Bh
#pragma unroll
                for (int f = 0; f < 4; f++)
                    ldsm4(af[f][0], af[f][1], af[f][2], af[f][3],
                          sptr(&Asl[wm*64 + 16*f + (lane & 15)][ks + ((lane >> 4) << 3)]));
#pragma unroll
                for (int mf = 0; mf < 4; mf++)
#pragma unroll
                    for (int nf = 0; nf < 4; nf++)
                        mma16816(acc[mf][nf], af[mf], bh[nf>>1][(nf&1)*2], bh[nf>>1][(nf&1)*2+1]);
            }
            __syncthreads();
        }
    }

    // ---- epilogue: +bias, relu, store f32 (+ optional bf16 split) ----
#pragma unroll
    for (int nf = 0; nf < 4; nf++) {
        int col = wn*32 + 8*nf + 2*q;
        float b0 = bias[col], b1 = bias[col + 1];
#pragma unroll
        for (int mf = 0; mf < 4; mf++) {
            int row0 = m0 + wm*64 + 16*mf + g;
            float v0 = fmaxf(acc[mf][nf][0] + b0, 0.f);
            float v1 = fmaxf(acc[mf][nf][1] + b1, 0.f);
            float v2 = fmaxf(acc[mf][nf][2] + b0, 0.f);
            float v3 = fmaxf(acc[mf][nf][3] + b1, 0.f);
            *(float2*)&C[(size_t)row0 * 128 + col]       = make_float2(v0, v1);
            *(float2*)&C[(size_t)(row0 + 8) * 128 + col] = make_float2(v2, v3);
            if (Ch) {
                bf16 h0,h1,h2,h3,l0,l1,l2,l3;
                bfsplit(v0,h0,l0); bfsplit(v1,h1,l1); bfsplit(v2,h2,l2); bfsplit(v3,h3,l3);
                *(__nv_bfloat162*)&Ch[(size_t)row0*128 + col]     = __halves2bfloat162(h0,h1);
                *(__nv_bfloat162*)&Ch[(size_t)(row0+8)*128 + col] = __halves2bfloat162(h2,h3);
                *(__nv_bfloat162*)&Cl[(size_t)row0*128 + col]     = __halves2bfloat162(l0,l1);
                *(__nv_bfloat162*)&Cl[(size_t)(row0+8)*128 + col] = __halves2bfloat162(l2,l3);
            }
        }
    }
}

// ---------------- LayerNorm over D=128, one warp per row; emits f32 + bf16 split
__global__ void ln_k(const float* __restrict__ in, const float* __restrict__ gam,
                     const float* __restrict__ bet, float* __restrict__ out)
{
    int wid = threadIdx.x >> 5, lane = threadIdx.x & 31;
    int row = blockIdx.x * 8 + wid;
    const float4* ip = (const float4*)(in + (size_t)row * 128);
    float4 v = ip[lane];
    float s  = v.x + v.y + v.z + v.w;
    float sq = v.x*v.x + v.y*v.y + v.z*v.z + v.w*v.w;
#pragma unroll
    for (int o = 16; o; o >>= 1) {
        s  += __shfl_xor_sync(0xffffffffu, s,  o);
        sq += __shfl_xor_sync(0xffffffffu, sq, o);
    }
    float mu  = s * (1.f/128.f);
    float var = sq * (1.f/128.f) - mu*mu;
    float inv = rsqrtf(var + 1e-5f);
    float4 gg = ((const float4*)gam)[lane];
    float4 bb = ((const float4*)bet)[lane];
    float4 o4;
    o4.x = (v.x - mu)*inv*gg.x + bb.x;
    o4.y = (v.y - mu)*inv*gg.y + bb.y;
    o4.z = (v.z - mu)*inv*gg.z + bb.z;
    o4.w = (v.w - mu)*inv*gg.w + bb.w;
    ((float4*)(out + (size_t)row * 128))[lane] = o4;
    size_t base = (size_t)row * 128 + lane * 4;
    bf16 h0,h1,h2,h3,l0,l1,l2,l3;
    bfsplit(o4.x,h0,l0); bfsplit(o4.y,h1,l1); bfsplit(o4.z,h2,l2); bfsplit(o4.w,h3,l3);
    *(__nv_bfloat162*)&g_lmh[base]   = __halves2bfloat162(h0,h1);
    *(__nv_bfloat162*)&g_lmh[base+2] = __halves2bfloat162(h2,h3);
    *(__nv_bfloat162*)&g_lml[base]   = __halves2bfloat162(l0,l1);
    *(__nv_bfloat162*)&g_lml[base+2] = __halves2bfloat162(l2,l3);
}

// ---------------- edge preprocessing ----------------
__global__ void hist_k(const void* __restrict__ ei, const void* __restrict__ et) {
    int i = blockIdx.x*blockDim.x + threadIdx.x;
    int stride = gridDim.x*blockDim.x;
    for (; i < Ee; i += stride) {
        int dst = load_int(ei, (long long)Ee + i);
        int rel = load_int(et, i);
        atomicAdd(&g_cnt[dst * Rr + rel], 1);
    }
}

// two-level scan: 96 blocks x 1024
__global__ void scan1_k() {
    __shared__ int wsum[32];
    int tid = threadIdx.x, lane = tid & 31, wid = tid >> 5;
    int gidx = blockIdx.x * 1024 + tid;
    int v = g_cnt[gidx];
    int x = v;
#pragma unroll
    for (int o = 1; o < 32; o <<= 1) {
        int t = __shfl_up_sync(0xffffffffu, x, o);
        if (lane >= o) x += t;
    }
    if (lane == 31) wsum[wid] = x;
    __syncthreads();
    if (wid == 0) {
        int w = wsum[lane];
#pragma unroll
        for (int o = 1; o < 32; o <<= 1) {
            int t = __shfl_up_sync(0xffffffffu, w, o);
            if (lane >= o) w += t;
        }
        wsum[lane] = w;
    }
    __syncthreads();
    int incl = x + (wid ? wsum[wid-1] : 0);
    g_off[gidx] = incl - v;                 // block-local exclusive
    if (tid == 1023) g_bsum[blockIdx.x] = incl;
}

__global__ void scan2_k() {   // 1 block, 128 threads: exclusive scan of 96 block sums
    __shared__ int wsum[4];
    int tid = threadIdx.x, lane = tid & 31, wid = tid >> 5;
    int v = (tid < 96) ? g_bsum[tid] : 0;
    int x = v;
#pragma unroll
    for (int o = 1; o < 32; o <<= 1) {
        int t = __shfl_up_sync(0xffffffffu, x, o);
        if (lane >= o) x += t;
    }
    if (lane == 31) wsum[wid] = x;
    __syncthreads();
    int pre = 0;
    for (int w = 0; w < wid; w++) pre += wsum[w];
    int incl = x + pre;
    if (tid < 96) g_bsum[tid] = incl - v;   // exclusive
    if (tid == 95) g_off[NRr] = incl;       // total
}

__global__ void scan3_k() {
    int gidx = blockIdx.x * 1024 + threadIdx.x;
    g_off[gidx] += g_bsum[blockIdx.x];
}

__global__ void scatter_k(const void* __restrict__ ei, const void* __restrict__ et) {
    int i = blockIdx.x*blockDim.x + threadIdx.x;
    int stride = gridDim.x*blockDim.x;
    for (; i < Ee; i += stride) {
        int dst = load_int(ei, (long long)Ee + i);
        int rel = load_int(et, i);
        int src = load_int(ei, i);
        int seg = dst * Rr + rel;
        int pos = g_off[seg] + atomicAdd(&g_cursor[seg], 1);
        g_srcs[pos] = src;
    }
}

// ---------------- per-segment mean aggregation -> bf16 hi/lo, no atomics -----
__global__ void agg_k(const float* __restrict__ x) {
    int warp = blockIdx.x * (blockDim.x >> 5) + (threadIdx.x >> 5);
    if (warp >= NRr) return;
    int lane = threadIdx.x & 31;
    int beg = g_off[warp], end = g_off[warp + 1];
    float a0 = 0.f, a1 = 0.f, a2 = 0.f, a3 = 0.f;
    for (int i = beg; i < end; i++) {
        const float* xr = x + (size_t)g_srcs[i] * 128;
        a0 += xr[lane];       a1 += xr[lane + 32];
        a2 += xr[lane + 64];  a3 += xr[lane + 96];
    }
    int c = end - beg;
    float inv = 1.f / (float)(c > 0 ? c : 1);
    int n = warp / Rr, r = warp % Rr;
    size_t base = (size_t)n * (Rr*Dd) + r * Dd;
    float v; bf16 h, l;
    v = a0*inv; bfsplit(v,h,l); g_aggh[base+lane]    = h; g_aggl[base+lane]    = l;
    v = a1*inv; bfsplit(v,h,l); g_aggh[base+lane+32] = h; g_aggl[base+lane+32] = l;
    v = a2*inv; bfsplit(v,h,l); g_aggh[base+lane+64] = h; g_aggl[base+lane+64] = l;
    v = a3*inv; bfsplit(v,h,l); g_aggh[base+lane+96] = h; g_aggl[base+lane+96] = l;
}

// ---------------- classifier + masked CE; warp per row ----------------
__global__ void cls_k(const float* __restrict__ lm, const float* __restrict__ gx,
                      const float* __restrict__ W, const float* __restrict__ cb,
                      const void* __restrict__ labels, const void* __restrict__ amask,
                      float* __restrict__ logits_out)
{
    __shared__ float s_nll[8];
    __shared__ float s_val[8];
    int wid = threadIdx.x >> 5, lane = threadIdx.x & 31;
    int row = blockIdx.x * 8 + wid;

    float4 f0, f1;
    if (lane < 16) {
        const float* p = lm + (size_t)row * 128 + lane * 8;
        f0 = *(const float4*)p; f1 = *(const float4*)(p + 4);
    } else {
        const float* p = gx + (size_t)row * 128 + (lane - 16) * 8;
        f0 = *(const float4*)p; f1 = *(const float4*)(p + 4);
    }
    float acc[8];
    const float4* W4 = (const float4*)W;   // [8][64 float4]
#pragma unroll
    for (int c = 0; c < 8; c++) {
        float4 w0 = W4[c*64 + lane*2];
        float4 w1 = W4[c*64 + lane*2 + 1];
        acc[c] = f0.x*w0.x + f0.y*w0.y + f0.z*w0.z + f0.w*w0.w
               + f1.x*w1.x + f1.y*w1.y + f1.z*w1.z + f1.w*w1.w;
    }
#pragma unroll
    for (int c = 0; c < 8; c++)
#pragma unroll
        for (int o = 16; o; o >>= 1)
            acc[c] += __shfl_xor_sync(0xffffffffu, acc[c], o);

    if (lane == 0) {
        float lg[8];
#pragma unroll
        for (int c = 0; c < 8; c++) lg[c] = acc[c] + cb[c];
        float mx = lg[0];
#pragma unroll
        for (int c = 1; c < 8; c++) mx = fmaxf(mx, lg[c]);
        float se = 0.f;
#pragma unroll
        for (int c = 0; c < 8; c++) se += expf(lg[c] - mx);
        float lse = mx + logf(se);
#pragma unroll
        for (int c = 0; c < 8; c++) logits_out[(size_t)row * 8 + c] = lg[c];
        int lab = load_int(labels, row);
        bool valid = (load_int(amask, row) == 1);
        s_nll[wid] = valid ? (lse - lg[lab]) : 0.f;
        s_val[wid] = valid ? 1.f : 0.f;
    }
    __syncthreads();
    if (threadIdx.x == 0) {
        float sn = 0.f, sv = 0.f;
#pragma unroll
        for (int i = 0; i < 8; i++) { sn += s_nll[i]; sv += s_val[i]; }
        atomicAdd(&g_loss[0], sn);
        atomicAdd(&g_loss[1], sv);
    }
}

__global__ void fin_k(float* __restrict__ out) {
    out[0] = g_loss[0] / fmaxf(g_loss[1], 1.f);
}

// ---------------- launch ----------------
extern "C" void kernel_launch(void* const* d_in, const int* in_sizes, int n_in,
                              void* d_out, int out_size)
{
    const float* outp   = (const float*)d_in[0];
    const void*  ei     = d_in[1];
    const void*  et     = d_in[2];
    const void*  amask  = d_in[3];
    const void*  labels = d_in[4];
    const float* lm_W   = (const float*)d_in[5];
    const float* lm_b   = (const float*)d_in[6];
    const float* ln_g   = (const float*)d_in[7];
    const float* ln_b   = (const float*)d_in[8];
    const float* W_rel  = (const float*)d_in[9];
    const float* W_root = (const float*)d_in[10];
    const float* conv_b = (const float*)d_in[11];
    const float* cls_W  = (const float*)d_in[12];
    const float* cls_b  = (const float*)d_in[13];
    float* out = (float*)d_out;

    void *p_lm, *p_x, *p_x2, *p_lg;
    void *p_Wth, *p_Wtl, *p_aggh, *p_aggl;
    void *p_lmh, *p_lml, *p_xh, *p_xl;
    void *p_Wrelh, *p_Wrell, *p_Wrooth, *p_Wrootl;
    cudaGetSymbolAddress(&p_lm,  g_lm);
    cudaGetSymbolAddress(&p_x,   g_x);
    cudaGetSymbolAddress(&p_x2,  g_x2);
    cudaGetSymbolAddress(&p_lg,  g_logits_scratch);
    cudaGetSymbolAddress(&p_Wth, g_Wth);
    cudaGetSymbolAddress(&p_Wtl, g_Wtl);
    cudaGetSymbolAddress(&p_aggh, g_aggh);
    cudaGetSymbolAddress(&p_aggl, g_aggl);
    cudaGetSymbolAddress(&p_lmh, g_lmh);
    cudaGetSymbolAddress(&p_lml, g_lml);
    cudaGetSymbolAddress(&p_xh,  g_xh);
    cudaGetSymbolAddress(&p_xl,  g_xl);
    cudaGetSymbolAddress(&p_Wrelh, g_Wrelh);
    cudaGetSymbolAddress(&p_Wrell, g_Wrell);
    cudaGetSymbolAddress(&p_Wrooth, g_Wrooth);
    cudaGetSymbolAddress(&p_Wrootl, g_Wrootl);

    float* lm  = (float*)p_lm;
    float* x1  = (float*)p_x;
    float* x2  = (float*)p_x2;
    bf16*  Wth = (bf16*)p_Wth;  bf16* Wtl = (bf16*)p_Wtl;
    bf16*  aggh = (bf16*)p_aggh; bf16* aggl = (bf16*)p_aggl;
    bf16*  lmh = (bf16*)p_lmh;  bf16* lml = (bf16*)p_lml;
    bf16*  xh  = (bf16*)p_xh;   bf16* xl  = (bf16*)p_xl;
    bf16*  Wrelh = (bf16*)p_Wrelh;   bf16* Wrell = (bf16*)p_Wrell;
    bf16*  Wrooth = (bf16*)p_Wrooth; bf16* Wrootl = (bf16*)p_Wrootl;

    // setup
    probe_k<<<1, 256>>>((const int*)ei);
    zero_k<<<96, 1024>>>();
    transWsplit_k<<<512, 256>>>(lm_W);
    splitW_k<<<96, 256>>>(W_rel,  NLAYERS*Rr*Dd*Dd, Wrelh,  Wrell);
    splitW_k<<<32, 256>>>(W_root, NLAYERS*Dd*Dd,    Wrooth, Wrootl);

    // LM head GEMM: f32 A split fused into tile load
    gemm3_k<<<Nn/128, 256>>>(outp, nullptr, nullptr, LMD, Wth, Wtl,
                             nullptr, nullptr, 0, nullptr, nullptr,
                             lm_b, x2, nullptr, nullptr);
    ln_k<<<Nn/8, 256>>>(x2, ln_g, ln_b, lm);

    // edge counting sort (two-level scan)
    hist_k<<<512, 256>>>(ei, et);
    scan1_k<<<96, 1024>>>();
    scan2_k<<<1, 128>>>();
    scan3_k<<<96, 1024>>>();
    scatter_k<<<512, 256>>>(ei, et);

    // layer 0
    agg_k<<<NRr/8, 256>>>(lm);
    gemm3_k<<<Nn/128, 256>>>(nullptr, aggh, aggl, Rr*Dd, Wrelh, Wrell,
                             lmh, lml, Dd, Wrooth, Wrootl,
                             conv_b, x1, xh, xl);
    // layer 1
    agg_k<<<NRr/8, 256>>>(x1);
    gemm3_k<<<Nn/128, 256>>>(nullptr, aggh, aggl, Rr*Dd, Wrelh + Rr*Dd*Dd, Wrell + Rr*Dd*Dd,
                             xh, xl, Dd, Wrooth + Dd*Dd, Wrootl + Dd*Dd,
                             conv_b + Dd, x2, nullptr, nullptr);

    // classifier + loss
    const int LOGITS = Nn * Cc;
    if (out_size >= LOGITS + 1) {
        cls_k<<<Nn/8, 256>>>(lm, x2, cls_W, cls_b, labels, amask, out + 1);
        fin_k<<<1, 1>>>(out);
    } else if (out_size >= LOGITS) {
        cls_k<<<Nn/8, 256>>>(lm, x2, cls_W, cls_b, labels, amask, out);
    } else {
        cls_k<<<Nn/8, 256>>>(lm, x2, cls_W, cls_b, labels, amask, (float*)p_lg);
        fin_k<<<1, 1>>>(out);
    }
}

// round 12
// speedup vs baseline: 1.2553x; 1.2553x over previous
#include <cuda_runtime.h>
#include <cuda_bf16.h>
#include <cstdint>

#define Bb 32
#define Ll 1024
#define LMD 1024
#define Dd 128
#define Rr 3
#define NLAYERS 2
#define Cc 8
#define Nn (Bb*Ll)          // 32768
#define Ee 524288
#define NRr (Nn*Rr)         // 98304

typedef __nv_bfloat16 bf16;

// ---------------- scratch (device globals; no allocations allowed) ----------
__device__ float g_lm[Nn*Dd];         // post-LN lm features (f32, for cls + agg)
__device__ bf16  g_lmh[Nn*Dd], g_lml[Nn*Dd];
__device__ float g_x[Nn*Dd];          // layer-0 output f32 (for agg gather + split src)
__device__ bf16  g_xh[Nn*Dd], g_xl[Nn*Dd];
__device__ float g_x2[Nn*Dd];         // pre-LN temp / layer-1 output
__device__ bf16  g_aggh[(size_t)Nn*Rr*Dd], g_aggl[(size_t)Nn*Rr*Dd];
__device__ bf16  g_Ah[(size_t)Nn*LMD], g_Al[(size_t)Nn*LMD];   // split LM input
__device__ bf16  g_Wth[LMD*Dd], g_Wtl[LMD*Dd];                 // lm_W^T split
__device__ bf16  g_Wrelh[NLAYERS*Rr*Dd*Dd], g_Wrell[NLAYERS*Rr*Dd*Dd];
__device__ bf16  g_Wrooth[NLAYERS*Dd*Dd], g_Wrootl[NLAYERS*Dd*Dd];
__device__ float g_logits_scratch[Nn*Cc];
__device__ int   g_cnt[NRr];
__device__ int   g_cursor[NRr];
__device__ int   g_off[NRr+1];
__device__ int   g_bsum[128];
__device__ int   g_srcs[Ee];
__device__ float g_loss[2];
__device__ int   g_is64;

// ---------------- small helpers ----------------
__device__ __forceinline__ uint32_t sptr(const void* p) {
    return (uint32_t)__cvta_generic_to_shared(p);
}
__device__ __forceinline__ void bfsplit(float v, bf16& h, bf16& l) {
    h = __float2bfloat16(v);
    l = __float2bfloat16(v - __bfloat162float(h));
}

__device__ __forceinline__ void ldsm4(uint32_t& r0, uint32_t& r1, uint32_t& r2, uint32_t& r3,
                                      uint32_t addr) {
    asm volatile("ldmatrix.sync.aligned.m8n8.x4.shared.b16 {%0,%1,%2,%3}, [%4];"
                 : "=r"(r0), "=r"(r1), "=r"(r2), "=r"(r3) : "r"(addr));
}
__device__ __forceinline__ void ldsm4t(uint32_t& r0, uint32_t& r1, uint32_t& r2, uint32_t& r3,
                                       uint32_t addr) {
    asm volatile("ldmatrix.sync.aligned.m8n8.x4.trans.shared.b16 {%0,%1,%2,%3}, [%4];"
                 : "=r"(r0), "=r"(r1), "=r"(r2), "=r"(r3) : "r"(addr));
}
__device__ __forceinline__ void mma16816(float* c, const uint32_t* a, uint32_t b0, uint32_t b1) {
    asm volatile("mma.sync.aligned.m16n8k16.row.col.f32.bf16.bf16.f32 "
                 "{%0,%1,%2,%3},{%4,%5,%6,%7},{%8,%9},{%0,%1,%2,%3};"
                 : "+f"(c[0]), "+f"(c[1]), "+f"(c[2]), "+f"(c[3])
                 : "r"(a[0]), "r"(a[1]), "r"(a[2]), "r"(a[3]), "r"(b0), "r"(b1));
}

// ---------------- int dtype probe ----------------
__global__ void probe_k(const int* __restrict__ p) {
    __shared__ int bad;
    if (threadIdx.x == 0) bad = 0;
    __syncthreads();
    for (int i = threadIdx.x; i < 1024; i += blockDim.x)
        if (p[2*i + 1] != 0) bad = 1;
    __syncthreads();
    if (threadIdx.x == 0) g_is64 = bad ? 0 : 1;
}
__device__ __forceinline__ int load_int(const void* p, long long idx) {
    if (g_is64) return (int)((const long long*)p)[idx];
    return ((const int*)p)[idx];
}

// ---------------- utility kernels ----------------
__global__ void zero_k() {
    int i = blockIdx.x*blockDim.x + threadIdx.x;
    int stride = gridDim.x*blockDim.x;
    for (; i < NRr; i += stride) { g_cnt[i] = 0; g_cursor[i] = 0; }
    if (blockIdx.x == 0 && threadIdx.x < 2) g_loss[threadIdx.x] = 0.f;
}

// lm_W [128][1024] -> Wt [1024][128], split into bf16 hi/lo. Output-indexed.
__global__ void transWsplit_k(const float* __restrict__ W) {
    int o = blockIdx.x*blockDim.x + threadIdx.x;     // 131072
    if (o >= LMD*Dd) return;
    int k = o >> 7, h = o & 127;
    float v = W[h*LMD + k];
    bf16 hi, lo; bfsplit(v, hi, lo);
    g_Wth[o] = hi; g_Wtl[o] = lo;
}

// generic elementwise split
__global__ void splitW_k(const float* __restrict__ src, int n, bf16* __restrict__ h, bf16* __restrict__ l) {
    int i = blockIdx.x*blockDim.x + threadIdx.x;
    int stride = gridDim.x*blockDim.x;
    for (; i < n; i += stride) {
        bf16 hi, lo; bfsplit(src[i], hi, lo);
        h[i] = hi; l[i] = lo;
    }
}

// big split: LM input [N x 1024] f32 -> bf16 hi/lo, 4 floats per thread iter
__global__ void splitA_k(const float* __restrict__ src) {
    size_t i = (size_t)blockIdx.x*blockDim.x + threadIdx.x;
    size_t stride = (size_t)gridDim.x*blockDim.x;
    const size_t n4 = (size_t)Nn*LMD/4;
    for (size_t j = i; j < n4; j += stride) {
        float4 v = ((const float4*)src)[j];
        bf16 h0,h1,h2,h3,l0,l1,l2,l3;
        bfsplit(v.x,h0,l0); bfsplit(v.y,h1,l1); bfsplit(v.z,h2,l2); bfsplit(v.w,h3,l3);
        ((__nv_bfloat162*)g_Ah)[2*j]   = __halves2bfloat162(h0,h1);
        ((__nv_bfloat162*)g_Ah)[2*j+1] = __halves2bfloat162(h2,h3);
        ((__nv_bfloat162*)g_Al)[2*j]   = __halves2bfloat162(l0,l1);
        ((__nv_bfloat162*)g_Al)[2*j+1] = __halves2bfloat162(l2,l3);
    }
}

// ---------------- tensor-core GEMM with 3xBF16 split (R10 4-pass structure) --
// C[M x 128] = relu( sum over parts of (Ah@Bh + Ah@Bl + Al@Bh) + bias )
// per part: pass (Ah, Bh+Bl dual) then (Al, Bh single).
// Block 128x128, BK=32, 256 threads = 8 warps (2 m x 4 n), warp tile 64x32.
__global__ __launch_bounds__(256, 2)
void gemm3_k(const bf16* __restrict__ A1h, const bf16* __restrict__ A1l, int K1,
             const bf16* __restrict__ B1h, const bf16* __restrict__ B1l,
             const bf16* __restrict__ A2h, const bf16* __restrict__ A2l, int K2,
             const bf16* __restrict__ B2h, const bf16* __restrict__ B2l,
             const float* __restrict__ bias, float* __restrict__ C,
             bf16* __restrict__ Ch, bf16* __restrict__ Cl)
{
    __shared__ bf16 As[128][40];        // pad 8 -> row stride 80B
    __shared__ bf16 Bsm[2][32][136];    // pad 8 -> row stride 272B

    const int tid  = threadIdx.x;
    const int wid  = tid >> 5;
    const int lane = tid & 31;
    const int wm   = wid >> 2;          // 0..1 -> m offset *64
    const int wn   = wid & 3;           // 0..3 -> n offset *32
    const int m0   = blockIdx.x * 128;
    const int g    = lane >> 2;
    const int q    = lane & 3;

    float acc[4][4][4];
#pragma unroll
    for (int i = 0; i < 4; i++)
#pragma unroll
        for (int j = 0; j < 4; j++)
#pragma unroll
            for (int r = 0; r < 4; r++) acc[i][j][r] = 0.f;

    // 4 passes: (A1h,B1h+B1l), (A1l,B1h), (A2h,B2h+B2l), (A2l,B2h)
#pragma unroll 1
    for (int pass = 0; pass < 4; pass++) {
        const bf16* Ap; const bf16* Bp0; const bf16* Bp1; int K;
        if      (pass == 0) { Ap = A1h; Bp0 = B1h; Bp1 = B1l; K = K1; }
        else if (pass == 1) { Ap = A1l; Bp0 = B1h; Bp1 = nullptr; K = K1; }
        else if (pass == 2) { Ap = A2h; Bp0 = B2h; Bp1 = B2l; K = K2; }
        else                { Ap = A2l; Bp0 = B2h; Bp1 = nullptr; K = K2; }
        if (Ap == nullptr || K == 0) continue;
        const bool dual = (Bp1 != nullptr);

#pragma unroll 1
        for (int kt = 0; kt < K; kt += 32) {
            // ---- load A tile 128x32 (512 16B-chunks, 2 iters) ----
            {
                int c = tid;
#pragma unroll
                for (int it = 0; it < 2; it++, c += 256) {
                    int row = c >> 2, cc = c & 3;
                    uint4 v = *(const uint4*)(Ap + (size_t)(m0 + row) * K + kt + cc*8);
                    *(uint4*)&As[row][cc*8] = v;
                }
            }
            // ---- load B tiles 32x128 ----
            {
                int c = tid;
#pragma unroll
                for (int it = 0; it < 2; it++, c += 256) {
                    int row = c >> 4, cc = c & 15;
                    uint4 v = *(const uint4*)(Bp0 + (size_t)(kt + row) * 128 + cc*8);
                    *(uint4*)&Bsm[0][row][cc*8] = v;
                }
                if (dual) {
                    c = tid;
#pragma unroll
                    for (int it = 0; it < 2; it++, c += 256) {
                        int row = c >> 4, cc = c & 15;
                        uint4 v = *(const uint4*)(Bp1 + (size_t)(kt + row) * 128 + cc*8);
                        *(uint4*)&Bsm[1][row][cc*8] = v;
                    }
                }
            }
            __syncthreads();

#pragma unroll
            for (int ks = 0; ks < 32; ks += 16) {
                uint32_t af[4][4];
#pragma unroll
                for (int f = 0; f < 4; f++)
                    ldsm4(af[f][0], af[f][1], af[f][2], af[f][3],
                          sptr(&As[wm*64 + 16*f + (lane & 15)][ks + ((lane >> 4) << 3)]));
                uint32_t bh[2][4];
#pragma unroll
                for (int t = 0; t < 2; t++)
                    ldsm4t(bh[t][0], bh[t][1], bh[t][2], bh[t][3],
                           sptr(&Bsm[0][ks + (lane & 15)][wn*32 + 16*t + ((lane >> 4) << 3)]));
#pragma unroll
                for (int mf = 0; mf < 4; mf++)
#pragma unroll
                    for (int nf = 0; nf < 4; nf++)
                        mma16816(acc[mf][nf], af[mf], bh[nf>>1][(nf&1)*2], bh[nf>>1][(nf&1)*2+1]);
                if (dual) {
                    uint32_t bl[2][4];
#pragma unroll
                    for (int t = 0; t < 2; t++)
                        ldsm4t(bl[t][0], bl[t][1], bl[t][2], bl[t][3],
                               sptr(&Bsm[1][ks + (lane & 15)][wn*32 + 16*t + ((lane >> 4) << 3)]));
#pragma unroll
                    for (int mf = 0; mf < 4; mf++)
#pragma unroll
                        for (int nf = 0; nf < 4; nf++)
                            mma16816(acc[mf][nf], af[mf], bl[nf>>1][(nf&1)*2], bl[nf>>1][(nf&1)*2+1]);
                }
            }
            __syncthreads();
        }
    }

    // ---- epilogue: +bias, relu, store f32 (+ optional bf16 split) ----
#pragma unroll
    for (int nf = 0; nf < 4; nf++) {
        int col = wn*32 + 8*nf + 2*q;
        float b0 = bias[col], b1 = bias[col + 1];
#pragma unroll
        for (int mf = 0; mf < 4; mf++) {
            int row0 = m0 + wm*64 + 16*mf + g;
            float v0 = fmaxf(acc[mf][nf][0] + b0, 0.f);
            float v1 = fmaxf(acc[mf][nf][1] + b1, 0.f);
            float v2 = fmaxf(acc[mf][nf][2] + b0, 0.f);
            float v3 = fmaxf(acc[mf][nf][3] + b1, 0.f);
            *(float2*)&C[(size_t)row0 * 128 + col]       = make_float2(v0, v1);
            *(float2*)&C[(size_t)(row0 + 8) * 128 + col] = make_float2(v2, v3);
            if (Ch) {
                bf16 h0,h1,h2,h3,l0,l1,l2,l3;
                bfsplit(v0,h0,l0); bfsplit(v1,h1,l1); bfsplit(v2,h2,l2); bfsplit(v3,h3,l3);
                *(__nv_bfloat162*)&Ch[(size_t)row0*128 + col]     = __halves2bfloat162(h0,h1);
                *(__nv_bfloat162*)&Ch[(size_t)(row0+8)*128 + col] = __halves2bfloat162(h2,h3);
                *(__nv_bfloat162*)&Cl[(size_t)row0*128 + col]     = __halves2bfloat162(l0,l1);
                *(__nv_bfloat162*)&Cl[(size_t)(row0+8)*128 + col] = __halves2bfloat162(l2,l3);
            }
        }
    }
}

// ---------------- LayerNorm over D=128, one warp per row; emits f32 + bf16 split
__global__ void ln_k(const float* __restrict__ in, const float* __restrict__ gam,
                     const float* __restrict__ bet, float* __restrict__ out)
{
    int wid = threadIdx.x >> 5, lane = threadIdx.x & 31;
    int row = blockIdx.x * 8 + wid;
    const float4* ip = (const float4*)(in + (size_t)row * 128);
    float4 v = ip[lane];
    float s  = v.x + v.y + v.z + v.w;
    float sq = v.x*v.x + v.y*v.y + v.z*v.z + v.w*v.w;
#pragma unroll
    for (int o = 16; o; o >>= 1) {
        s  += __shfl_xor_sync(0xffffffffu, s,  o);
        sq += __shfl_xor_sync(0xffffffffu, sq, o);
    }
    float mu  = s * (1.f/128.f);
    float var = sq * (1.f/128.f) - mu*mu;
    float inv = rsqrtf(var + 1e-5f);
    float4 gg = ((const float4*)gam)[lane];
    float4 bb = ((const float4*)bet)[lane];
    float4 o4;
    o4.x = (v.x - mu)*inv*gg.x + bb.x;
    o4.y = (v.y - mu)*inv*gg.y + bb.y;
    o4.z = (v.z - mu)*inv*gg.z + bb.z;
    o4.w = (v.w - mu)*inv*gg.w + bb.w;
    ((float4*)(out + (size_t)row * 128))[lane] = o4;
    size_t base = (size_t)row * 128 + lane * 4;
    bf16 h0,h1,h2,h3,l0,l1,l2,l3;
    bfsplit(o4.x,h0,l0); bfsplit(o4.y,h1,l1); bfsplit(o4.z,h2,l2); bfsplit(o4.w,h3,l3);
    *(__nv_bfloat162*)&g_lmh[base]   = __halves2bfloat162(h0,h1);
    *(__nv_bfloat162*)&g_lmh[base+2] = __halves2bfloat162(h2,h3);
    *(__nv_bfloat162*)&g_lml[base]   = __halves2bfloat162(l0,l1);
    *(__nv_bfloat162*)&g_lml[base+2] = __halves2bfloat162(l2,l3);
}

// ---------------- edge preprocessing ----------------
__global__ void hist_k(const void* __restrict__ ei, const void* __restrict__ et) {
    int i = blockIdx.x*blockDim.x + threadIdx.x;
    int stride = gridDim.x*blockDim.x;
    for (; i < Ee; i += stride) {
        int dst = load_int(ei, (long long)Ee + i);
        int rel = load_int(et, i);
        atomicAdd(&g_cnt[dst * Rr + rel], 1);
    }
}

// two-level scan: 96 blocks x 1024
__global__ void scan1_k() {
    __shared__ int wsum[32];
    int tid = threadIdx.x, lane = tid & 31, wid = tid >> 5;
    int gidx = blockIdx.x * 1024 + tid;
    int v = g_cnt[gidx];
    int x = v;
#pragma unroll
    for (int o = 1; o < 32; o <<= 1) {
        int t = __shfl_up_sync(0xffffffffu, x, o);
        if (lane >= o) x += t;
    }
    if (lane == 31) wsum[wid] = x;
    __syncthreads();
    if (wid == 0) {
        int w = wsum[lane];
#pragma unroll
        for (int o = 1; o < 32; o <<= 1) {
            int t = __shfl_up_sync(0xffffffffu, w, o);
            if (lane >= o) w += t;
        }
        wsum[lane] = w;
    }
    __syncthreads();
    int incl = x + (wid ? wsum[wid-1] : 0);
    g_off[gidx] = incl - v;                 // block-local exclusive
    if (tid == 1023) g_bsum[blockIdx.x] = incl;
}

__global__ void scan2_k() {   // 1 block, 128 threads: exclusive scan of 96 block sums
    __shared__ int wsum[4];
    int tid = threadIdx.x, lane = tid & 31, wid = tid >> 5;
    int v = (tid < 96) ? g_bsum[tid] : 0;
    int x = v;
#pragma unroll
    for (int o = 1; o < 32; o <<= 1) {
        int t = __shfl_up_sync(0xffffffffu, x, o);
        if (lane >= o) x += t;
    }
    if (lane == 31) wsum[wid] = x;
    __syncthreads();
    int pre = 0;
    for (int w = 0; w < wid; w++) pre += wsum[w];
    int incl = x + pre;
    if (tid < 96) g_bsum[tid] = incl - v;   // exclusive
    if (tid == 95) g_off[NRr] = incl;       // total
}

__global__ void scan3_k() {
    int gidx = blockIdx.x * 1024 + threadIdx.x;
    g_off[gidx] += g_bsum[blockIdx.x];
}

__global__ void scatter_k(const void* __restrict__ ei, const void* __restrict__ et) {
    int i = blockIdx.x*blockDim.x + threadIdx.x;
    int stride = gridDim.x*blockDim.x;
    for (; i < Ee; i += stride) {
        int dst = load_int(ei, (long long)Ee + i);
        int rel = load_int(et, i);
        int src = load_int(ei, i);
        int seg = dst * Rr + rel;
        int pos = g_off[seg] + atomicAdd(&g_cursor[seg], 1);
        g_srcs[pos] = src;
    }
}

// ---------------- per-segment mean aggregation -> bf16 hi/lo, no atomics -----
__global__ void agg_k(const float* __restrict__ x) {
    int warp = blockIdx.x * (blockDim.x >> 5) + (threadIdx.x >> 5);
    if (warp >= NRr) return;
    int lane = threadIdx.x & 31;
    int beg = g_off[warp], end = g_off[warp + 1];
    float a0 = 0.f, a1 = 0.f, a2 = 0.f, a3 = 0.f;
    for (int i = beg; i < end; i++) {
        const float* xr = x + (size_t)g_srcs[i] * 128;
        a0 += xr[lane];       a1 += xr[lane + 32];
        a2 += xr[lane + 64];  a3 += xr[lane + 96];
    }
    int c = end - beg;
    float inv = 1.f / (float)(c > 0 ? c : 1);
    int n = warp / Rr, r = warp % Rr;
    size_t base = (size_t)n * (Rr*Dd) + r * Dd;
    float v; bf16 h, l;
    v = a0*inv; bfsplit(v,h,l); g_aggh[base+lane]    = h; g_aggl[base+lane]    = l;
    v = a1*inv; bfsplit(v,h,l); g_aggh[base+lane+32] = h; g_aggl[base+lane+32] = l;
    v = a2*inv; bfsplit(v,h,l); g_aggh[base+lane+64] = h; g_aggl[base+lane+64] = l;
    v = a3*inv; bfsplit(v,h,l); g_aggh[base+lane+96] = h; g_aggl[base+lane+96] = l;
}

// ---------------- classifier + masked CE; warp per row ----------------
__global__ void cls_k(const float* __restrict__ lm, const float* __restrict__ gx,
                      const float* __restrict__ W, const float* __restrict__ cb,
                      const void* __restrict__ labels, const void* __restrict__ amask,
                      float* __restrict__ logits_out)
{
    __shared__ float s_nll[8];
    __shared__ float s_val[8];
    int wid = threadIdx.x >> 5, lane = threadIdx.x & 31;
    int row = blockIdx.x * 8 + wid;

    float4 f0, f1;
    if (lane < 16) {
        const float* p = lm + (size_t)row * 128 + lane * 8;
        f0 = *(const float4*)p; f1 = *(const float4*)(p + 4);
    } else {
        const float* p = gx + (size_t)row * 128 + (lane - 16) * 8;
        f0 = *(const float4*)p; f1 = *(const float4*)(p + 4);
    }
    float acc[8];
    const float4* W4 = (const float4*)W;   // [8][64 float4]
#pragma unroll
    for (int c = 0; c < 8; c++) {
        float4 w0 = W4[c*64 + lane*2];
        float4 w1 = W4[c*64 + lane*2 + 1];
        acc[c] = f0.x*w0.x + f0.y*w0.y + f0.z*w0.z + f0.w*w0.w
               + f1.x*w1.x + f1.y*w1.y + f1.z*w1.z + f1.w*w1.w;
    }
#pragma unroll
    for (int c = 0; c < 8; c++)
#pragma unroll
        for (int o = 16; o; o >>= 1)
            acc[c] += __shfl_xor_sync(0xffffffffu, acc[c], o);

    if (lane == 0) {
        float lg[8];
#pragma unroll
        for (int c = 0; c < 8; c++) lg[c] = acc[c] + cb[c];
        float mx = lg[0];
#pragma unroll
        for (int c = 1; c < 8; c++) mx = fmaxf(mx, lg[c]);
        float se = 0.f;
#pragma unroll
        for (int c = 0; c < 8; c++) se += expf(lg[c] - mx);
        float lse = mx + logf(se);
#pragma unroll
        for (int c = 0; c < 8; c++) logits_out[(size_t)row * 8 + c] = lg[c];
        int lab = load_int(labels, row);
        bool valid = (load_int(amask, row) == 1);
        s_nll[wid] = valid ? (lse - lg[lab]) : 0.f;
        s_val[wid] = valid ? 1.f : 0.f;
    }
    __syncthreads();
    if (threadIdx.x == 0) {
        float sn = 0.f, sv = 0.f;
#pragma unroll
        for (int i = 0; i < 8; i++) { sn += s_nll[i]; sv += s_val[i]; }
        atomicAdd(&g_loss[0], sn);
        atomicAdd(&g_loss[1], sv);
    }
}

__global__ void fin_k(float* __restrict__ out) {
    out[0] = g_loss[0] / fmaxf(g_loss[1], 1.f);
}

// ---------------- launch ----------------
extern "C" void kernel_launch(void* const* d_in, const int* in_sizes, int n_in,
                              void* d_out, int out_size)
{
    const float* outp   = (const float*)d_in[0];
    const void*  ei     = d_in[1];
    const void*  et     = d_in[2];
    const void*  amask  = d_in[3];
    const void*  labels = d_in[4];
    const float* lm_W   = (const float*)d_in[5];
    const float* lm_b   = (const float*)d_in[6];
    const float* ln_g   = (const float*)d_in[7];
    const float* ln_b   = (const float*)d_in[8];
    const float* W_rel  = (const float*)d_in[9];
    const float* W_root = (const float*)d_in[10];
    const float* conv_b = (const float*)d_in[11];
    const float* cls_W  = (const float*)d_in[12];
    const float* cls_b  = (const float*)d_in[13];
    float* out = (float*)d_out;

    void *p_lm, *p_x, *p_x2, *p_lg;
    void *p_Ah, *p_Al, *p_Wth, *p_Wtl, *p_aggh, *p_aggl;
    void *p_lmh, *p_lml, *p_xh, *p_xl;
    void *p_Wrelh, *p_Wrell, *p_Wrooth, *p_Wrootl;
    cudaGetSymbolAddress(&p_lm,  g_lm);
    cudaGetSymbolAddress(&p_x,   g_x);
    cudaGetSymbolAddress(&p_x2,  g_x2);
    cudaGetSymbolAddress(&p_lg,  g_logits_scratch);
    cudaGetSymbolAddress(&p_Ah,  g_Ah);
    cudaGetSymbolAddress(&p_Al,  g_Al);
    cudaGetSymbolAddress(&p_Wth, g_Wth);
    cudaGetSymbolAddress(&p_Wtl, g_Wtl);
    cudaGetSymbolAddress(&p_aggh, g_aggh);
    cudaGetSymbolAddress(&p_aggl, g_aggl);
    cudaGetSymbolAddress(&p_lmh, g_lmh);
    cudaGetSymbolAddress(&p_lml, g_lml);
    cudaGetSymbolAddress(&p_xh,  g_xh);
    cudaGetSymbolAddress(&p_xl,  g_xl);
    cudaGetSymbolAddress(&p_Wrelh, g_Wrelh);
    cudaGetSymbolAddress(&p_Wrell, g_Wrell);
    cudaGetSymbolAddress(&p_Wrooth, g_Wrooth);
    cudaGetSymbolAddress(&p_Wrootl, g_Wrootl);

    float* lm  = (float*)p_lm;
    float* x1  = (float*)p_x;
    float* x2  = (float*)p_x2;
    bf16*  Ah  = (bf16*)p_Ah;   bf16* Al  = (bf16*)p_Al;
    bf16*  Wth = (bf16*)p_Wth;  bf16* Wtl = (bf16*)p_Wtl;
    bf16*  aggh = (bf16*)p_aggh; bf16* aggl = (bf16*)p_aggl;
    bf16*  lmh = (bf16*)p_lmh;  bf16* lml = (bf16*)p_lml;
    bf16*  xh  = (bf16*)p_xh;   bf16* xl  = (bf16*)p_xl;
    bf16*  Wrelh = (bf16*)p_Wrelh;   bf16* Wrell = (bf16*)p_Wrell;
    bf16*  Wrooth = (bf16*)p_Wrooth; bf16* Wrootl = (bf16*)p_Wrootl;

    // setup
    probe_k<<<1, 256>>>((const int*)ei);
    zero_k<<<96, 1024>>>();
    transWsplit_k<<<512, 256>>>(lm_W);
    splitW_k<<<96, 256>>>(W_rel,  NLAYERS*Rr*Dd*Dd, Wrelh,  Wrell);
    splitW_k<<<32, 256>>>(W_root, NLAYERS*Dd*Dd,    Wrooth, Wrootl);
    splitA_k<<<2048, 256>>>(outp);

    // LM head GEMM (bf16 3-split) -> x2 (pre-LN), then LN -> lm (+ lmh/lml)
    gemm3_k<<<Nn/128, 256>>>(Ah, Al, LMD, Wth, Wtl,
                             nullptr, nullptr, 0, nullptr, nullptr,
                             lm_b, x2, nullptr, nullptr);
    ln_k<<<Nn/8, 256>>>(x2, ln_g, ln_b, lm);

    // edge counting sort (two-level scan)
    hist_k<<<512, 256>>>(ei, et);
    scan1_k<<<96, 1024>>>();
    scan2_k<<<1, 128>>>();
    scan3_k<<<96, 1024>>>();
    scatter_k<<<512, 256>>>(ei, et);

    // layer 0
    agg_k<<<NRr/8, 256>>>(lm);
    gemm3_k<<<Nn/128, 256>>>(aggh, aggl, Rr*Dd, Wrelh, Wrell,
                             lmh, lml, Dd, Wrooth, Wrootl,
                             conv_b, x1, xh, xl);
    // layer 1
    agg_k<<<NRr/8, 256>>>(x1);
    gemm3_k<<<Nn/128, 256>>>(aggh, aggl, Rr*Dd, Wrelh + Rr*Dd*Dd, Wrell + Rr*Dd*Dd,
                             xh, xl, Dd, Wrooth + Dd*Dd, Wrootl + Dd*Dd,
                             conv_b + Dd, x2, nullptr, nullptr);

    // classifier + loss
    const int LOGITS = Nn * Cc;
    if (out_size >= LOGITS + 1) {
        cls_k<<<Nn/8, 256>>>(lm, x2, cls_W, cls_b, labels, amask, out + 1);
        fin_k<<<1, 1>>>(out);
    } else if (out_size >= LOGITS) {
        cls_k<<<Nn/8, 256>>>(lm, x2, cls_W, cls_b, labels, amask, out);
    } else {
        cls_k<<<Nn/8, 256>>>(lm, x2, cls_W, cls_b, labels, amask, (float*)p_lg);
        fin_k<<<1, 1>>>(out);
    }
}

// round 13
// speedup vs baseline: 1.3236x; 1.0544x over previous
#include <cuda_runtime.h>
#include <cuda_bf16.h>
#include <cstdint>

#define Bb 32
#define Ll 1024
#define LMD 1024
#define Dd 128
#define Rr 3
#define NLAYERS 2
#define Cc 8
#define Nn (Bb*Ll)          // 32768
#define Ee 524288
#define NRr (Nn*Rr)         // 98304

typedef __nv_bfloat16 bf16;

// ---------------- scratch (device globals; no allocations allowed) ----------
__device__ float g_lm[Nn*Dd];
__device__ bf16  g_lmh[Nn*Dd], g_lml[Nn*Dd];
__device__ float g_x[Nn*Dd];
__device__ bf16  g_xh[Nn*Dd], g_xl[Nn*Dd];
__device__ float g_x2[Nn*Dd];
__device__ bf16  g_aggh[(size_t)Nn*Rr*Dd], g_aggl[(size_t)Nn*Rr*Dd];
__device__ bf16  g_Ah[(size_t)Nn*LMD], g_Al[(size_t)Nn*LMD];
__device__ bf16  g_Wth[LMD*Dd], g_Wtl[LMD*Dd];
__device__ bf16  g_Wrelh[NLAYERS*Rr*Dd*Dd], g_Wrell[NLAYERS*Rr*Dd*Dd];
__device__ bf16  g_Wrooth[NLAYERS*Dd*Dd], g_Wrootl[NLAYERS*Dd*Dd];
__device__ float g_logits_scratch[Nn*Cc];
__device__ int   g_cnt[NRr];
__device__ int   g_cursor[NRr];
__device__ int   g_off[NRr+1];
__device__ int   g_bsum[128];
__device__ int   g_srcs[Ee];
__device__ float g_loss[2];
__device__ int   g_is64;

// ---------------- small helpers ----------------
__device__ __forceinline__ uint32_t sptr(const void* p) {
    return (uint32_t)__cvta_generic_to_shared(p);
}
__device__ __forceinline__ void bfsplit(float v, bf16& h, bf16& l) {
    h = __float2bfloat16(v);
    l = __float2bfloat16(v - __bfloat162float(h));
}
__device__ __forceinline__ void cpasync16(uint32_t dst, const void* src) {
    asm volatile("cp.async.cg.shared.global [%0], [%1], 16;" :: "r"(dst), "l"(src));
}
#define CP_COMMIT() asm volatile("cp.async.commit_group;")
#define CP_WAIT0()  asm volatile("cp.async.wait_group 0;")

__device__ __forceinline__ void ldsm4(uint32_t& r0, uint32_t& r1, uint32_t& r2, uint32_t& r3,
                                      uint32_t addr) {
    asm volatile("ldmatrix.sync.aligned.m8n8.x4.shared.b16 {%0,%1,%2,%3}, [%4];"
                 : "=r"(r0), "=r"(r1), "=r"(r2), "=r"(r3) : "r"(addr));
}
__device__ __forceinline__ void ldsm4t(uint32_t& r0, uint32_t& r1, uint32_t& r2, uint32_t& r3,
                                       uint32_t addr) {
    asm volatile("ldmatrix.sync.aligned.m8n8.x4.trans.shared.b16 {%0,%1,%2,%3}, [%4];"
                 : "=r"(r0), "=r"(r1), "=r"(r2), "=r"(r3) : "r"(addr));
}
__device__ __forceinline__ void mma16816(float* c, const uint32_t* a, uint32_t b0, uint32_t b1) {
    asm volatile("mma.sync.aligned.m16n8k16.row.col.f32.bf16.bf16.f32 "
                 "{%0,%1,%2,%3},{%4,%5,%6,%7},{%8,%9},{%0,%1,%2,%3};"
                 : "+f"(c[0]), "+f"(c[1]), "+f"(c[2]), "+f"(c[3])
                 : "r"(a[0]), "r"(a[1]), "r"(a[2]), "r"(a[3]), "r"(b0), "r"(b1));
}

// ---------------- int dtype probe ----------------
__global__ void probe_k(const int* __restrict__ p) {
    __shared__ int bad;
    if (threadIdx.x == 0) bad = 0;
    __syncthreads();
    for (int i = threadIdx.x; i < 1024; i += blockDim.x)
        if (p[2*i + 1] != 0) bad = 1;
    __syncthreads();
    if (threadIdx.x == 0) g_is64 = bad ? 0 : 1;
}
__device__ __forceinline__ int load_int(const void* p, long long idx) {
    if (g_is64) return (int)((const long long*)p)[idx];
    return ((const int*)p)[idx];
}

// ---------------- utility kernels ----------------
__global__ void zero_k() {
    int i = blockIdx.x*blockDim.x + threadIdx.x;
    int stride = gridDim.x*blockDim.x;
    for (; i < NRr; i += stride) { g_cnt[i] = 0; g_cursor[i] = 0; }
    if (blockIdx.x == 0 && threadIdx.x < 2) g_loss[threadIdx.x] = 0.f;
}

__global__ void transWsplit_k(const float* __restrict__ W) {
    int o = blockIdx.x*blockDim.x + threadIdx.x;
    if (o >= LMD*Dd) return;
    int k = o >> 7, h = o & 127;
    float v = W[h*LMD + k];
    bf16 hi, lo; bfsplit(v, hi, lo);
    g_Wth[o] = hi; g_Wtl[o] = lo;
}

__global__ void splitW_k(const float* __restrict__ src, int n, bf16* __restrict__ h, bf16* __restrict__ l) {
    int i = blockIdx.x*blockDim.x + threadIdx.x;
    int stride = gridDim.x*blockDim.x;
    for (; i < n; i += stride) {
        bf16 hi, lo; bfsplit(src[i], hi, lo);
        h[i] = hi; l[i] = lo;
    }
}

__global__ void splitA_k(const float* __restrict__ src) {
    size_t i = (size_t)blockIdx.x*blockDim.x + threadIdx.x;
    size_t stride = (size_t)gridDim.x*blockDim.x;
    const size_t n4 = (size_t)Nn*LMD/4;
    for (size_t j = i; j < n4; j += stride) {
        float4 v = ((const float4*)src)[j];
        bf16 h0,h1,h2,h3,l0,l1,l2,l3;
        bfsplit(v.x,h0,l0); bfsplit(v.y,h1,l1); bfsplit(v.z,h2,l2); bfsplit(v.w,h3,l3);
        ((__nv_bfloat162*)g_Ah)[2*j]   = __halves2bfloat162(h0,h1);
        ((__nv_bfloat162*)g_Ah)[2*j+1] = __halves2bfloat162(h2,h3);
        ((__nv_bfloat162*)g_Al)[2*j]   = __halves2bfloat162(l0,l1);
        ((__nv_bfloat162*)g_Al)[2*j+1] = __halves2bfloat162(l2,l3);
    }
}

// ---------------- tensor-core GEMM, 3xBF16 split, cp.async 2-stage pipeline --
// 4 passes: (A1h,B1h+B1l), (A1l,B1h), (A2h,B2h+B2l), (A2l,B2h)
// Block 128x128, BK=32, 256 threads = 8 warps (2m x 4n), warp tile 64x32.
// Dynamic smem: As[2][128][40] + Bs0[2][32][136] + Bs1[2][32][136] = 55296 B.
#define GEMM_SMEM (2*128*40*2 + 2*32*136*2 + 2*32*136*2)

__global__ __launch_bounds__(256, 2)
void gemm3_k(const bf16* __restrict__ A1h, const bf16* __restrict__ A1l, int K1,
             const bf16* __restrict__ B1h, const bf16* __restrict__ B1l,
             const bf16* __restrict__ A2h, const bf16* __restrict__ A2l, int K2,
             const bf16* __restrict__ B2h, const bf16* __restrict__ B2l,
             const float* __restrict__ bias, float* __restrict__ C,
             bf16* __restrict__ Ch, bf16* __restrict__ Cl)
{
    extern __shared__ bf16 smem[];
    bf16 (*As)[128][40]  = (bf16(*)[128][40])(smem);
    bf16 (*Bs0)[32][136] = (bf16(*)[32][136])(smem + 2*128*40);
    bf16 (*Bs1)[32][136] = (bf16(*)[32][136])(smem + 2*128*40 + 2*32*136);

    const int tid  = threadIdx.x;
    const int wid  = tid >> 5;
    const int lane = tid & 31;
    const int wm   = wid >> 2;
    const int wn   = wid & 3;
    const int m0   = blockIdx.x * 128;
    const int g    = lane >> 2;
    const int q    = lane & 3;

    // per-thread load coordinates (16B chunks)
    const int a_row0 = tid >> 2,        a_cc = (tid & 3) * 8;        // +64 rows second chunk
    const int b_row0 = tid >> 4,        b_cc = (tid & 15) * 8;       // +16 rows second chunk

    float acc[4][4][4];
#pragma unroll
    for (int i = 0; i < 4; i++)
#pragma unroll
        for (int j = 0; j < 4; j++)
#pragma unroll
            for (int r = 0; r < 4; r++) acc[i][j][r] = 0.f;

#pragma unroll 1
    for (int pass = 0; pass < 4; pass++) {
        const bf16* Ap; const bf16* Bp0; const bf16* Bp1; int K;
        if      (pass == 0) { Ap = A1h; Bp0 = B1h; Bp1 = B1l; K = K1; }
        else if (pass == 1) { Ap = A1l; Bp0 = B1h; Bp1 = nullptr; K = K1; }
        else if (pass == 2) { Ap = A2h; Bp0 = B2h; Bp1 = B2l; K = K2; }
        else                { Ap = A2l; Bp0 = B2h; Bp1 = nullptr; K = K2; }
        if (Ap == nullptr || K == 0) continue;
        const bool dual = (Bp1 != nullptr);
        const int T = K >> 5;   // tiles of 32

        // prefetch tile 0 into stage 0
        {
            cpasync16(sptr(&As[0][a_row0][a_cc]),      Ap + (size_t)(m0 + a_row0) * K + a_cc);
            cpasync16(sptr(&As[0][a_row0 + 64][a_cc]), Ap + (size_t)(m0 + a_row0 + 64) * K + a_cc);
            cpasync16(sptr(&Bs0[0][b_row0][b_cc]),      Bp0 + (size_t)b_row0 * 128 + b_cc);
            cpasync16(sptr(&Bs0[0][b_row0 + 16][b_cc]), Bp0 + (size_t)(b_row0 + 16) * 128 + b_cc);
            if (dual) {
                cpasync16(sptr(&Bs1[0][b_row0][b_cc]),      Bp1 + (size_t)b_row0 * 128 + b_cc);
                cpasync16(sptr(&Bs1[0][b_row0 + 16][b_cc]), Bp1 + (size_t)(b_row0 + 16) * 128 + b_cc);
            }
            CP_COMMIT();
        }

#pragma unroll 1
        for (int t = 0; t < T; t++) {
            CP_WAIT0();
            __syncthreads();
            const int s = t & 1;
            if (t + 1 < T) {
                const int ns = s ^ 1;
                const int kt = (t + 1) << 5;
                cpasync16(sptr(&As[ns][a_row0][a_cc]),      Ap + (size_t)(m0 + a_row0) * K + kt + a_cc);
                cpasync16(sptr(&As[ns][a_row0 + 64][a_cc]), Ap + (size_t)(m0 + a_row0 + 64) * K + kt + a_cc);
                cpasync16(sptr(&Bs0[ns][b_row0][b_cc]),      Bp0 + (size_t)(kt + b_row0) * 128 + b_cc);
                cpasync16(sptr(&Bs0[ns][b_row0 + 16][b_cc]), Bp0 + (size_t)(kt + b_row0 + 16) * 128 + b_cc);
                if (dual) {
                    cpasync16(sptr(&Bs1[ns][b_row0][b_cc]),      Bp1 + (size_t)(kt + b_row0) * 128 + b_cc);
                    cpasync16(sptr(&Bs1[ns][b_row0 + 16][b_cc]), Bp1 + (size_t)(kt + b_row0 + 16) * 128 + b_cc);
                }
                CP_COMMIT();
            }

#pragma unroll
            for (int ks = 0; ks < 32; ks += 16) {
                uint32_t af[4][4];
#pragma unroll
                for (int f = 0; f < 4; f++)
                    ldsm4(af[f][0], af[f][1], af[f][2], af[f][3],
                          sptr(&As[s][wm*64 + 16*f + (lane & 15)][ks + ((lane >> 4) << 3)]));
                uint32_t bh[2][4];
#pragma unroll
                for (int tt = 0; tt < 2; tt++)
                    ldsm4t(bh[tt][0], bh[tt][1], bh[tt][2], bh[tt][3],
                           sptr(&Bs0[s][ks + (lane & 15)][wn*32 + 16*tt + ((lane >> 4) << 3)]));
#pragma unroll
                for (int mf = 0; mf < 4; mf++)
#pragma unroll
                    for (int nf = 0; nf < 4; nf++)
                        mma16816(acc[mf][nf], af[mf], bh[nf>>1][(nf&1)*2], bh[nf>>1][(nf&1)*2+1]);
                if (dual) {
                    uint32_t bl[2][4];
#pragma unroll
                    for (int tt = 0; tt < 2; tt++)
                        ldsm4t(bl[tt][0], bl[tt][1], bl[tt][2], bl[tt][3],
                               sptr(&Bs1[s][ks + (lane & 15)][wn*32 + 16*tt + ((lane >> 4) << 3)]));
#pragma unroll
                    for (int mf = 0; mf < 4; mf++)
#pragma unroll
                        for (int nf = 0; nf < 4; nf++)
                            mma16816(acc[mf][nf], af[mf], bl[nf>>1][(nf&1)*2], bl[nf>>1][(nf&1)*2+1]);
                }
            }
        }
        __syncthreads();   // last compute of this pass must finish before next pass prefetch
    }

    // ---- epilogue: +bias, relu, store f32 (+ optional bf16 split) ----
#pragma unroll
    for (int nf = 0; nf < 4; nf++) {
        int col = wn*32 + 8*nf + 2*q;
        float b0 = bias[col], b1 = bias[col + 1];
#pragma unroll
        for (int mf = 0; mf < 4; mf++) {
            int row0 = m0 + wm*64 + 16*mf + g;
            float v0 = fmaxf(acc[mf][nf][0] + b0, 0.f);
            float v1 = fmaxf(acc[mf][nf][1] + b1, 0.f);
            float v2 = fmaxf(acc[mf][nf][2] + b0, 0.f);
            float v3 = fmaxf(acc[mf][nf][3] + b1, 0.f);
            *(float2*)&C[(size_t)row0 * 128 + col]       = make_float2(v0, v1);
            *(float2*)&C[(size_t)(row0 + 8) * 128 + col] = make_float2(v2, v3);
            if (Ch) {
                bf16 h0,h1,h2,h3,l0,l1,l2,l3;
                bfsplit(v0,h0,l0); bfsplit(v1,h1,l1); bfsplit(v2,h2,l2); bfsplit(v3,h3,l3);
                *(__nv_bfloat162*)&Ch[(size_t)row0*128 + col]     = __halves2bfloat162(h0,h1);
                *(__nv_bfloat162*)&Ch[(size_t)(row0+8)*128 + col] = __halves2bfloat162(h2,h3);
                *(__nv_bfloat162*)&Cl[(size_t)row0*128 + col]     = __halves2bfloat162(l0,l1);
                *(__nv_bfloat162*)&Cl[(size_t)(row0+8)*128 + col] = __halves2bfloat162(l2,l3);
            }
        }
    }
}

// ---------------- LayerNorm over D=128, one warp per row; emits f32 + bf16 split
__global__ void ln_k(const float* __restrict__ in, const float* __restrict__ gam,
                     const float* __restrict__ bet, float* __restrict__ out)
{
    int wid = threadIdx.x >> 5, lane = threadIdx.x & 31;
    int row = blockIdx.x * 8 + wid;
    const float4* ip = (const float4*)(in + (size_t)row * 128);
    float4 v = ip[lane];
    float s  = v.x + v.y + v.z + v.w;
    float sq = v.x*v.x + v.y*v.y + v.z*v.z + v.w*v.w;
#pragma unroll
    for (int o = 16; o; o >>= 1) {
        s  += __shfl_xor_sync(0xffffffffu, s,  o);
        sq += __shfl_xor_sync(0xffffffffu, sq, o);
    }
    float mu  = s * (1.f/128.f);
    float var = sq * (1.f/128.f) - mu*mu;
    float inv = rsqrtf(var + 1e-5f);
    float4 gg = ((const float4*)gam)[lane];
    float4 bb = ((const float4*)bet)[lane];
    float4 o4;
    o4.x = (v.x - mu)*inv*gg.x + bb.x;
    o4.y = (v.y - mu)*inv*gg.y + bb.y;
    o4.z = (v.z - mu)*inv*gg.z + bb.z;
    o4.w = (v.w - mu)*inv*gg.w + bb.w;
    ((float4*)(out + (size_t)row * 128))[lane] = o4;
    size_t base = (size_t)row * 128 + lane * 4;
    bf16 h0,h1,h2,h3,l0,l1,l2,l3;
    bfsplit(o4.x,h0,l0); bfsplit(o4.y,h1,l1); bfsplit(o4.z,h2,l2); bfsplit(o4.w,h3,l3);
    *(__nv_bfloat162*)&g_lmh[base]   = __halves2bfloat162(h0,h1);
    *(__nv_bfloat162*)&g_lmh[base+2] = __halves2bfloat162(h2,h3);
    *(__nv_bfloat162*)&g_lml[base]   = __halves2bfloat162(l0,l1);
    *(__nv_bfloat162*)&g_lml[base+2] = __halves2bfloat162(l2,l3);
}

// ---------------- edge preprocessing ----------------
__global__ void hist_k(const void* __restrict__ ei, const void* __restrict__ et) {
    int i = blockIdx.x*blockDim.x + threadIdx.x;
    int stride = gridDim.x*blockDim.x;
    for (; i < Ee; i += stride) {
        int dst = load_int(ei, (long long)Ee + i);
        int rel = load_int(et, i);
        atomicAdd(&g_cnt[dst * Rr + rel], 1);
    }
}

__global__ void scan1_k() {
    __shared__ int wsum[32];
    int tid = threadIdx.x, lane = tid & 31, wid = tid >> 5;
    int gidx = blockIdx.x * 1024 + tid;
    int v = g_cnt[gidx];
    int x = v;
#pragma unroll
    for (int o = 1; o < 32; o <<= 1) {
        int t = __shfl_up_sync(0xffffffffu, x, o);
        if (lane >= o) x += t;
    }
    if (lane == 31) wsum[wid] = x;
    __syncthreads();
    if (wid == 0) {
        int w = wsum[lane];
#pragma unroll
        for (int o = 1; o < 32; o <<= 1) {
            int t = __shfl_up_sync(0xffffffffu, w, o);
            if (lane >= o) w += t;
        }
        wsum[lane] = w;
    }
    __syncthreads();
    int incl = x + (wid ? wsum[wid-1] : 0);
    g_off[gidx] = incl - v;
    if (tid == 1023) g_bsum[blockIdx.x] = incl;
}

__global__ void scan2_k() {
    __shared__ int wsum[4];
    int tid = threadIdx.x, lane = tid & 31, wid = tid >> 5;
    int v = (tid < 96) ? g_bsum[tid] : 0;
    int x = v;
#pragma unroll
    for (int o = 1; o < 32; o <<= 1) {
        int t = __shfl_up_sync(0xffffffffu, x, o);
        if (lane >= o) x += t;
    }
    if (lane == 31) wsum[wid] = x;
    __syncthreads();
    int pre = 0;
    for (int w = 0; w < wid; w++) pre += wsum[w];
    int incl = x + pre;
    if (tid < 96) g_bsum[tid] = incl - v;
    if (tid == 95) g_off[NRr] = incl;
}

__global__ void scan3_k() {
    int gidx = blockIdx.x * 1024 + threadIdx.x;
    g_off[gidx] += g_bsum[blockIdx.x];
}

__global__ void scatter_k(const void* __restrict__ ei, const void* __restrict__ et) {
    int i = blockIdx.x*blockDim.x + threadIdx.x;
    int stride = gridDim.x*blockDim.x;
    for (; i < Ee; i += stride) {
        int dst = load_int(ei, (long long)Ee + i);
        int rel = load_int(et, i);
        int src = load_int(ei, i);
        int seg = dst * Rr + rel;
        int pos = g_off[seg] + atomicAdd(&g_cursor[seg], 1);
        g_srcs[pos] = src;
    }
}

// ---------------- per-segment mean aggregation -> bf16 hi/lo, no atomics -----
__global__ void agg_k(const float* __restrict__ x) {
    int warp = blockIdx.x * (blockDim.x >> 5) + (threadIdx.x >> 5);
    if (warp >= NRr) return;
    int lane = threadIdx.x & 31;
    int beg = g_off[warp], end = g_off[warp + 1];
    float a0 = 0.f, a1 = 0.f, a2 = 0.f, a3 = 0.f;
    for (int i = beg; i < end; i++) {
        const float* xr = x + (size_t)g_srcs[i] * 128;
        a0 += xr[lane];       a1 += xr[lane + 32];
        a2 += xr[lane + 64];  a3 += xr[lane + 96];
    }
    int c = end - beg;
    float inv = 1.f / (float)(c > 0 ? c : 1);
    int n = warp / Rr, r = warp % Rr;
    size_t base = (size_t)n * (Rr*Dd) + r * Dd;
    float v; bf16 h, l;
    v = a0*inv; bfsplit(v,h,l); g_aggh[base+lane]    = h; g_aggl[base+lane]    = l;
    v = a1*inv; bfsplit(v,h,l); g_aggh[base+lane+32] = h; g_aggl[base+lane+32] = l;
    v = a2*inv; bfsplit(v,h,l); g_aggh[base+lane+64] = h; g_aggl[base+lane+64] = l;
    v = a3*inv; bfsplit(v,h,l); g_aggh[base+lane+96] = h; g_aggl[base+lane+96] = l;
}

// ---------------- classifier + masked CE; warp per row ----------------
__global__ void cls_k(const float* __restrict__ lm, const float* __restrict__ gx,
                      const float* __restrict__ W, const float* __restrict__ cb,
                      const void* __restrict__ labels, const void* __restrict__ amask,
                      float* __restrict__ logits_out)
{
    __shared__ float s_nll[8];
    __shared__ float s_val[8];
    int wid = threadIdx.x >> 5, lane = threadIdx.x & 31;
    int row = blockIdx.x * 8 + wid;

    float4 f0, f1;
    if (lane < 16) {
        const float* p = lm + (size_t)row * 128 + lane * 8;
        f0 = *(const float4*)p; f1 = *(const float4*)(p + 4);
    } else {
        const float* p = gx + (size_t)row * 128 + (lane - 16) * 8;
        f0 = *(const float4*)p; f1 = *(const float4*)(p + 4);
    }
    float acc[8];
    const float4* W4 = (const float4*)W;
#pragma unroll
    for (int c = 0; c < 8; c++) {
        float4 w0 = W4[c*64 + lane*2];
        float4 w1 = W4[c*64 + lane*2 + 1];
        acc[c] = f0.x*w0.x + f0.y*w0.y + f0.z*w0.z + f0.w*w0.w
               + f1.x*w1.x + f1.y*w1.y + f1.z*w1.z + f1.w*w1.w;
    }
#pragma unroll
    for (int c = 0; c < 8; c++)
#pragma unroll
        for (int o = 16; o; o >>= 1)
            acc[c] += __shfl_xor_sync(0xffffffffu, acc[c], o);

    if (lane == 0) {
        float lg[8];
#pragma unroll
        for (int c = 0; c < 8; c++) lg[c] = acc[c] + cb[c];
        float mx = lg[0];
#pragma unroll
        for (int c = 1; c < 8; c++) mx = fmaxf(mx, lg[c]);
        float se = 0.f;
#pragma unroll
        for (int c = 0; c < 8; c++) se += expf(lg[c] - mx);
        float lse = mx + logf(se);
#pragma unroll
        for (int c = 0; c < 8; c++) logits_out[(size_t)row * 8 + c] = lg[c];
        int lab = load_int(labels, row);
        bool valid = (load_int(amask, row) == 1);
        s_nll[wid] = valid ? (lse - lg[lab]) : 0.f;
        s_val[wid] = valid ? 1.f : 0.f;
    }
    __syncthreads();
    if (threadIdx.x == 0) {
        float sn = 0.f, sv = 0.f;
#pragma unroll
        for (int i = 0; i < 8; i++) { sn += s_nll[i]; sv += s_val[i]; }
        atomicAdd(&g_loss[0], sn);
        atomicAdd(&g_loss[1], sv);
    }
}

__global__ void fin_k(float* __restrict__ out) {
    out[0] = g_loss[0] / fmaxf(g_loss[1], 1.f);
}

// ---------------- launch ----------------
extern "C" void kernel_launch(void* const* d_in, const int* in_sizes, int n_in,
                              void* d_out, int out_size)
{
    const float* outp   = (const float*)d_in[0];
    const void*  ei     = d_in[1];
    const void*  et     = d_in[2];
    const void*  amask  = d_in[3];
    const void*  labels = d_in[4];
    const float* lm_W   = (const float*)d_in[5];
    const float* lm_b   = (const float*)d_in[6];
    const float* ln_g   = (const float*)d_in[7];
    const float* ln_b   = (const float*)d_in[8];
    const float* W_rel  = (const float*)d_in[9];
    const float* W_root = (const float*)d_in[10];
    const float* conv_b = (const float*)d_in[11];
    const float* cls_W  = (const float*)d_in[12];
    const float* cls_b  = (const float*)d_in[13];
    float* out = (float*)d_out;

    static bool attr_set = false;
    if (!attr_set) {
        cudaFuncSetAttribute(gemm3_k, cudaFuncAttributeMaxDynamicSharedMemorySize, GEMM_SMEM);
        attr_set = true;
    }

    void *p_lm, *p_x, *p_x2, *p_lg;
    void *p_Ah, *p_Al, *p_Wth, *p_Wtl, *p_aggh, *p_aggl;
    void *p_lmh, *p_lml, *p_xh, *p_xl;
    void *p_Wrelh, *p_Wrell, *p_Wrooth, *p_Wrootl;
    cudaGetSymbolAddress(&p_lm,  g_lm);
    cudaGetSymbolAddress(&p_x,   g_x);
    cudaGetSymbolAddress(&p_x2,  g_x2);
    cudaGetSymbolAddress(&p_lg,  g_logits_scratch);
    cudaGetSymbolAddress(&p_Ah,  g_Ah);
    cudaGetSymbolAddress(&p_Al,  g_Al);
    cudaGetSymbolAddress(&p_Wth, g_Wth);
    cudaGetSymbolAddress(&p_Wtl, g_Wtl);
    cudaGetSymbolAddress(&p_aggh, g_aggh);
    cudaGetSymbolAddress(&p_aggl, g_aggl);
    cudaGetSymbolAddress(&p_lmh, g_lmh);
    cudaGetSymbolAddress(&p_lml, g_lml);
    cudaGetSymbolAddress(&p_xh,  g_xh);
    cudaGetSymbolAddress(&p_xl,  g_xl);
    cudaGetSymbolAddress(&p_Wrelh, g_Wrelh);
    cudaGetSymbolAddress(&p_Wrell, g_Wrell);
    cudaGetSymbolAddress(&p_Wrooth, g_Wrooth);
    cudaGetSymbolAddress(&p_Wrootl, g_Wrootl);

    float* lm  = (float*)p_lm;
    float* x1  = (float*)p_x;
    float* x2  = (float*)p_x2;
    bf16*  Ah  = (bf16*)p_Ah;   bf16* Al  = (bf16*)p_Al;
    bf16*  Wth = (bf16*)p_Wth;  bf16* Wtl = (bf16*)p_Wtl;
    bf16*  aggh = (bf16*)p_aggh; bf16* aggl = (bf16*)p_aggl;
    bf16*  lmh = (bf16*)p_lmh;  bf16* lml = (bf16*)p_lml;
    bf16*  xh  = (bf16*)p_xh;   bf16* xl  = (bf16*)p_xl;
    bf16*  Wrelh = (bf16*)p_Wrelh;   bf16* Wrell = (bf16*)p_Wrell;
    bf16*  Wrooth = (bf16*)p_Wrooth; bf16* Wrootl = (bf16*)p_Wrootl;

    // setup
    probe_k<<<1, 256>>>((const int*)ei);
    zero_k<<<96, 1024>>>();
    transWsplit_k<<<512, 256>>>(lm_W);
    splitW_k<<<96, 256>>>(W_rel,  NLAYERS*Rr*Dd*Dd, Wrelh,  Wrell);
    splitW_k<<<32, 256>>>(W_root, NLAYERS*Dd*Dd,    Wrooth, Wrootl);
    splitA_k<<<2048, 256>>>(outp);

    // LM head GEMM (bf16 3-split, pipelined) -> x2 (pre-LN), then LN
    gemm3_k<<<Nn/128, 256, GEMM_SMEM>>>(Ah, Al, LMD, Wth, Wtl,
                             nullptr, nullptr, 0, nullptr, nullptr,
                             lm_b, x2, nullptr, nullptr);
    ln_k<<<Nn/8, 256>>>(x2, ln_g, ln_b, lm);

    // edge counting sort (two-level scan)
    hist_k<<<512, 256>>>(ei, et);
    scan1_k<<<96, 1024>>>();
    scan2_k<<<1, 128>>>();
    scan3_k<<<96, 1024>>>();
    scatter_k<<<512, 256>>>(ei, et);

    // layer 0
    agg_k<<<NRr/8, 256>>>(lm);
    gemm3_k<<<Nn/128, 256, GEMM_SMEM>>>(aggh, aggl, Rr*Dd, Wrelh, Wrell,
                             lmh, lml, Dd, Wrooth, Wrootl,
                             conv_b, x1, xh, xl);
    // layer 1
    agg_k<<<NRr/8, 256>>>(x1);
    gemm3_k<<<Nn/128, 256, GEMM_SMEM>>>(aggh, aggl, Rr*Dd, Wrelh + Rr*Dd*Dd, Wrell + Rr*Dd*Dd,
                             xh, xl, Dd, Wrooth + Dd*Dd, Wrootl + Dd*Dd,
                             conv_b + Dd, x2, nullptr, nullptr);

    // classifier + loss
    const int LOGITS = Nn * Cc;
    if (out_size >= LOGITS + 1) {
        cls_k<<<Nn/8, 256>>>(lm, x2, cls_W, cls_b, labels, amask, out + 1);
        fin_k<<<1, 1>>>(out);
    } else if (out_size >= LOGITS) {
        cls_k<<<Nn/8, 256>>>(lm, x2, cls_W, cls_b, labels, amask, out);
    } else {
        cls_k<<<Nn/8, 256>>>(lm, x2, cls_W, cls_b, labels, amask, (float*)p_lg);
        fin_k<<<1, 1>>>(out);
    }
}

// round 14
// speedup vs baseline: 1.5102x; 1.1410x over previous
#include <cuda_runtime.h>
#include <cuda_bf16.h>
#include <cstdint>

#define Bb 32
#define Ll 1024
#define LMD 1024
#define Dd 128
#define Rr 3
#define NLAYERS 2
#define Cc 8
#define Nn (Bb*Ll)          // 32768
#define Ee 524288
#define NRr (Nn*Rr)         // 98304

typedef __nv_bfloat16 bf16;

// ---------------- scratch (device globals; no allocations allowed) ----------
__device__ float g_lm[Nn*Dd];
__device__ bf16  g_lmh[Nn*Dd], g_lml[Nn*Dd];
__device__ float g_x[Nn*Dd];
__device__ bf16  g_xh[Nn*Dd], g_xl[Nn*Dd];
__device__ float g_x2[Nn*Dd];
__device__ bf16  g_aggh[(size_t)Nn*Rr*Dd], g_aggl[(size_t)Nn*Rr*Dd];
__device__ bf16  g_Wth[LMD*Dd], g_Wtl[LMD*Dd];
__device__ bf16  g_Wrelh[NLAYERS*Rr*Dd*Dd], g_Wrell[NLAYERS*Rr*Dd*Dd];
__device__ bf16  g_Wrooth[NLAYERS*Dd*Dd], g_Wrootl[NLAYERS*Dd*Dd];
__device__ float g_logits_scratch[Nn*Cc];
__device__ int   g_cnt[NRr];
__device__ int   g_cursor[NRr];
__device__ int   g_off[NRr+1];
__device__ int   g_bsum[128];
__device__ int   g_srcs[Ee];
__device__ float g_loss[2];
__device__ int   g_is64;

// ---------------- small helpers ----------------
__device__ __forceinline__ uint32_t sptr(const void* p) {
    return (uint32_t)__cvta_generic_to_shared(p);
}
__device__ __forceinline__ void bfsplit(float v, bf16& h, bf16& l) {
    h = __float2bfloat16(v);
    l = __float2bfloat16(v - __bfloat162float(h));
}
__device__ __forceinline__ void cpasync16(uint32_t dst, const void* src) {
    asm volatile("cp.async.cg.shared.global [%0], [%1], 16;" :: "r"(dst), "l"(src));
}
#define CP_COMMIT() asm volatile("cp.async.commit_group;")
#define CP_WAIT0()  asm volatile("cp.async.wait_group 0;")

__device__ __forceinline__ void ldsm4(uint32_t& r0, uint32_t& r1, uint32_t& r2, uint32_t& r3,
                                      uint32_t addr) {
    asm volatile("ldmatrix.sync.aligned.m8n8.x4.shared.b16 {%0,%1,%2,%3}, [%4];"
                 : "=r"(r0), "=r"(r1), "=r"(r2), "=r"(r3) : "r"(addr));
}
__device__ __forceinline__ void ldsm4t(uint32_t& r0, uint32_t& r1, uint32_t& r2, uint32_t& r3,
                                       uint32_t addr) {
    asm volatile("ldmatrix.sync.aligned.m8n8.x4.trans.shared.b16 {%0,%1,%2,%3}, [%4];"
                 : "=r"(r0), "=r"(r1), "=r"(r2), "=r"(r3) : "r"(addr));
}
__device__ __forceinline__ void mma16816(float* c, const uint32_t* a, uint32_t b0, uint32_t b1) {
    asm volatile("mma.sync.aligned.m16n8k16.row.col.f32.bf16.bf16.f32 "
                 "{%0,%1,%2,%3},{%4,%5,%6,%7},{%8,%9},{%0,%1,%2,%3};"
                 : "+f"(c[0]), "+f"(c[1]), "+f"(c[2]), "+f"(c[3])
                 : "r"(a[0]), "r"(a[1]), "r"(a[2]), "r"(a[3]), "r"(b0), "r"(b1));
}

// ---------------- int dtype probe ----------------
__global__ void probe_k(const int* __restrict__ p) {
    __shared__ int bad;
    if (threadIdx.x == 0) bad = 0;
    __syncthreads();
    for (int i = threadIdx.x; i < 1024; i += blockDim.x)
        if (p[2*i + 1] != 0) bad = 1;
    __syncthreads();
    if (threadIdx.x == 0) g_is64 = bad ? 0 : 1;
}
__device__ __forceinline__ int load_int(const void* p, long long idx) {
    if (g_is64) return (int)((const long long*)p)[idx];
    return ((const int*)p)[idx];
}

// ---------------- merged setup: zero + transW split + W_rel/W_root splits ----
__global__ void setup_k(const float* __restrict__ lm_W,
                        const float* __restrict__ W_rel,
                        const float* __restrict__ W_root) {
    int i = blockIdx.x*blockDim.x + threadIdx.x;
    int stride = gridDim.x*blockDim.x;
    for (; i < LMD*Dd; i += stride) {           // 131072, largest range
        if (i < NRr) { g_cnt[i] = 0; g_cursor[i] = 0; }
        // transposed lm_W split
        {
            int k = i >> 7, h = i & 127;
            float v = lm_W[h*LMD + k];
            bf16 hi, lo; bfsplit(v, hi, lo);
            g_Wth[i] = hi; g_Wtl[i] = lo;
        }
        if (i < NLAYERS*Rr*Dd*Dd) {             // 98304
            bf16 hi, lo; bfsplit(W_rel[i], hi, lo);
            g_Wrelh[i] = hi; g_Wrell[i] = lo;
        }
        if (i < NLAYERS*Dd*Dd) {                // 32768
            bf16 hi, lo; bfsplit(W_root[i], hi, lo);
            g_Wrooth[i] = hi; g_Wrootl[i] = lo;
        }
        if (i < 2) g_loss[i] = 0.f;
    }
}

// ---------------- tensor-core GEMM, 3xBF16 split, cp.async 2-stage pipeline --
// Mode 1 (A1f != null): A is f32; split to bf16 hi/lo in smem after cp.async;
//                       single K-loop computing Ah@Bh + Ah@Bl + Al@Bh.
// Mode 2: pre-split bf16 A; 4 passes as in R12.
// Block 128x128, BK=32, 256 threads = 8 warps (2m x 4n), warp tile 64x32.
#define GEMM_SMEM_BF16 (2*128*40*2 + 2*32*136*2 + 2*32*136*2)               // 55296
#define GEMM_SMEM_F32  (2*128*36*4 + 128*40*2 + 128*40*2 + 2*32*136*2*2)    // 92160

__global__ __launch_bounds__(256, 2)
void gemm3_k(const float* __restrict__ A1f,
             const bf16* __restrict__ A1h, const bf16* __restrict__ A1l, int K1,
             const bf16* __restrict__ B1h, const bf16* __restrict__ B1l,
             const bf16* __restrict__ A2h, const bf16* __restrict__ A2l, int K2,
             const bf16* __restrict__ B2h, const bf16* __restrict__ B2l,
             const float* __restrict__ bias, float* __restrict__ C,
             bf16* __restrict__ Ch, bf16* __restrict__ Cl)
{
    extern __shared__ bf16 smem[];

    const int tid  = threadIdx.x;
    const int wid  = tid >> 5;
    const int lane = tid & 31;
    const int wm   = wid >> 2;
    const int wn   = wid & 3;
    const int m0   = blockIdx.x * 128;
    const int g    = lane >> 2;
    const int q    = lane & 3;

    const int b_row0 = tid >> 4, b_cc = (tid & 15) * 8;

    float acc[4][4][4];
#pragma unroll
    for (int i = 0; i < 4; i++)
#pragma unroll
        for (int j = 0; j < 4; j++)
#pragma unroll
            for (int r = 0; r < 4; r++) acc[i][j][r] = 0.f;

    if (A1f) {
        // ---------------- f32-A mode (LM head) ----------------
        float (*Af32)[128][36] = (float(*)[128][36])(smem);
        bf16  (*Ash)[40]       = (bf16(*)[40])(smem + 2*128*36*2);           // bf16 units
        bf16  (*Asl)[40]       = (bf16(*)[40])(smem + 2*128*36*2 + 128*40);
        bf16  (*Bs0)[32][136]  = (bf16(*)[32][136])(smem + 2*128*36*2 + 2*128*40);
        bf16  (*Bs1)[32][136]  = (bf16(*)[32][136])(smem + 2*128*36*2 + 2*128*40 + 2*32*136);

        const int K = K1;
        const int T = K >> 5;
        // f32 A tile: 128 rows x 32 floats = 1024 16B-chunks, 4 per thread
        const int af_row = tid >> 3, af_cc = (tid & 7) * 4;   // +32 rows x4

        // prefetch tile 0
        {
#pragma unroll
            for (int r = 0; r < 4; r++)
                cpasync16(sptr(&Af32[0][af_row + 32*r][af_cc]),
                          A1f + (size_t)(m0 + af_row + 32*r) * K + af_cc);
            cpasync16(sptr(&Bs0[0][b_row0][b_cc]),      B1h + (size_t)b_row0 * 128 + b_cc);
            cpasync16(sptr(&Bs0[0][b_row0 + 16][b_cc]), B1h + (size_t)(b_row0 + 16) * 128 + b_cc);
            cpasync16(sptr(&Bs1[0][b_row0][b_cc]),      B1l + (size_t)b_row0 * 128 + b_cc);
            cpasync16(sptr(&Bs1[0][b_row0 + 16][b_cc]), B1l + (size_t)(b_row0 + 16) * 128 + b_cc);
            CP_COMMIT();
        }

#pragma unroll 1
        for (int t = 0; t < T; t++) {
            CP_WAIT0();
            __syncthreads();
            const int s = t & 1;
            if (t + 1 < T) {
                const int ns = s ^ 1;
                const int kt = (t + 1) << 5;
#pragma unroll
                for (int r = 0; r < 4; r++)
                    cpasync16(sptr(&Af32[ns][af_row + 32*r][af_cc]),
                              A1f + (size_t)(m0 + af_row + 32*r) * K + kt + af_cc);
                cpasync16(sptr(&Bs0[ns][b_row0][b_cc]),      B1h + (size_t)(kt + b_row0) * 128 + b_cc);
                cpasync16(sptr(&Bs0[ns][b_row0 + 16][b_cc]), B1h + (size_t)(kt + b_row0 + 16) * 128 + b_cc);
                cpasync16(sptr(&Bs1[ns][b_row0][b_cc]),      B1l + (size_t)(kt + b_row0) * 128 + b_cc);
                cpasync16(sptr(&Bs1[ns][b_row0 + 16][b_cc]), B1l + (size_t)(kt + b_row0 + 16) * 128 + b_cc);
                CP_COMMIT();
            }
            // convert Af32[s] -> Ash/Asl (single-buffered; prev MMA done via top sync)
#pragma unroll
            for (int r = 0; r < 4; r++) {
                int row = af_row + 32*r;
                float4 v = *(float4*)&Af32[s][row][af_cc];
                bf16 h0,h1,h2,h3,l0,l1,l2,l3;
                bfsplit(v.x,h0,l0); bfsplit(v.y,h1,l1); bfsplit(v.z,h2,l2); bfsplit(v.w,h3,l3);
                *(__nv_bfloat162*)&Ash[row][af_cc]     = __halves2bfloat162(h0,h1);
                *(__nv_bfloat162*)&Ash[row][af_cc + 2] = __halves2bfloat162(h2,h3);
                *(__nv_bfloat162*)&Asl[row][af_cc]     = __halves2bfloat162(l0,l1);
                *(__nv_bfloat162*)&Asl[row][af_cc + 2] = __halves2bfloat162(l2,l3);
            }
            __syncthreads();

#pragma unroll
            for (int ks = 0; ks < 32; ks += 16) {
                uint32_t af[4][4];
#pragma unroll
                for (int f = 0; f < 4; f++)
                    ldsm4(af[f][0], af[f][1], af[f][2], af[f][3],
                          sptr(&Ash[wm*64 + 16*f + (lane & 15)][ks + ((lane >> 4) << 3)]));
                uint32_t bh[2][4], bl[2][4];
#pragma unroll
                for (int tt = 0; tt < 2; tt++) {
                    ldsm4t(bh[tt][0], bh[tt][1], bh[tt][2], bh[tt][3],
                           sptr(&Bs0[s][ks + (lane & 15)][wn*32 + 16*tt + ((lane >> 4) << 3)]));
                    ldsm4t(bl[tt][0], bl[tt][1], bl[tt][2], bl[tt][3],
                           sptr(&Bs1[s][ks + (lane & 15)][wn*32 + 16*tt + ((lane >> 4) << 3)]));
                }
#pragma unroll
                for (int mf = 0; mf < 4; mf++)
#pragma unroll
                    for (int nf = 0; nf < 4; nf++) {
                        mma16816(acc[mf][nf], af[mf], bh[nf>>1][(nf&1)*2], bh[nf>>1][(nf&1)*2+1]);
                        mma16816(acc[mf][nf], af[mf], bl[nf>>1][(nf&1)*2], bl[nf>>1][(nf&1)*2+1]);
                    }
                // A-lo fragments, reuse regs
#pragma unroll
                for (int f = 0; f < 4; f++)
                    ldsm4(af[f][0], af[f][1], af[f][2], af[f][3],
                          sptr(&Asl[wm*64 + 16*f + (lane & 15)][ks + ((lane >> 4) << 3)]));
#pragma unroll
                for (int mf = 0; mf < 4; mf++)
#pragma unroll
                    for (int nf = 0; nf < 4; nf++)
                        mma16816(acc[mf][nf], af[mf], bh[nf>>1][(nf&1)*2], bh[nf>>1][(nf&1)*2+1]);
            }
        }
    } else {
        // ---------------- pre-split bf16 mode, 4 passes (R12) ----------------
        bf16 (*As)[128][40]  = (bf16(*)[128][40])(smem);
        bf16 (*Bs0)[32][136] = (bf16(*)[32][136])(smem + 2*128*40);
        bf16 (*Bs1)[32][136] = (bf16(*)[32][136])(smem + 2*128*40 + 2*32*136);
        const int a_row0 = tid >> 2, a_cc = (tid & 3) * 8;

#pragma unroll 1
        for (int pass = 0; pass < 4; pass++) {
            const bf16* Ap; const bf16* Bp0; const bf16* Bp1; int K;
            if      (pass == 0) { Ap = A1h; Bp0 = B1h; Bp1 = B1l; K = K1; }
            else if (pass == 1) { Ap = A1l; Bp0 = B1h; Bp1 = nullptr; K = K1; }
            else if (pass == 2) { Ap = A2h; Bp0 = B2h; Bp1 = B2l; K = K2; }
            else                { Ap = A2l; Bp0 = B2h; Bp1 = nullptr; K = K2; }
            if (Ap == nullptr || K == 0) continue;
            const bool dual = (Bp1 != nullptr);
            const int T = K >> 5;

            {
                cpasync16(sptr(&As[0][a_row0][a_cc]),      Ap + (size_t)(m0 + a_row0) * K + a_cc);
                cpasync16(sptr(&As[0][a_row0 + 64][a_cc]), Ap + (size_t)(m0 + a_row0 + 64) * K + a_cc);
                cpasync16(sptr(&Bs0[0][b_row0][b_cc]),      Bp0 + (size_t)b_row0 * 128 + b_cc);
                cpasync16(sptr(&Bs0[0][b_row0 + 16][b_cc]), Bp0 + (size_t)(b_row0 + 16) * 128 + b_cc);
                if (dual) {
                    cpasync16(sptr(&Bs1[0][b_row0][b_cc]),      Bp1 + (size_t)b_row0 * 128 + b_cc);
                    cpasync16(sptr(&Bs1[0][b_row0 + 16][b_cc]), Bp1 + (size_t)(b_row0 + 16) * 128 + b_cc);
                }
                CP_COMMIT();
            }

#pragma unroll 1
            for (int t = 0; t < T; t++) {
                CP_WAIT0();
                __syncthreads();
                const int s = t & 1;
                if (t + 1 < T) {
                    const int ns = s ^ 1;
                    const int kt = (t + 1) << 5;
                    cpasync16(sptr(&As[ns][a_row0][a_cc]),      Ap + (size_t)(m0 + a_row0) * K + kt + a_cc);
                    cpasync16(sptr(&As[ns][a_row0 + 64][a_cc]), Ap + (size_t)(m0 + a_row0 + 64) * K + kt + a_cc);
                    cpasync16(sptr(&Bs0[ns][b_row0][b_cc]),      Bp0 + (size_t)(kt + b_row0) * 128 + b_cc);
                    cpasync16(sptr(&Bs0[ns][b_row0 + 16][b_cc]), Bp0 + (size_t)(kt + b_row0 + 16) * 128 + b_cc);
                    if (dual) {
                        cpasync16(sptr(&Bs1[ns][b_row0][b_cc]),      Bp1 + (size_t)(kt + b_row0) * 128 + b_cc);
                        cpasync16(sptr(&Bs1[ns][b_row0 + 16][b_cc]), Bp1 + (size_t)(kt + b_row0 + 16) * 128 + b_cc);
                    }
                    CP_COMMIT();
                }

#pragma unroll
                for (int ks = 0; ks < 32; ks += 16) {
                    uint32_t af[4][4];
#pragma unroll
                    for (int f = 0; f < 4; f++)
                        ldsm4(af[f][0], af[f][1], af[f][2], af[f][3],
                              sptr(&As[s][wm*64 + 16*f + (lane & 15)][ks + ((lane >> 4) << 3)]));
                    uint32_t bh[2][4];
#pragma unroll
                    for (int tt = 0; tt < 2; tt++)
                        ldsm4t(bh[tt][0], bh[tt][1], bh[tt][2], bh[tt][3],
                               sptr(&Bs0[s][ks + (lane & 15)][wn*32 + 16*tt + ((lane >> 4) << 3)]));
#pragma unroll
                    for (int mf = 0; mf < 4; mf++)
#pragma unroll
                        for (int nf = 0; nf < 4; nf++)
                            mma16816(acc[mf][nf], af[mf], bh[nf>>1][(nf&1)*2], bh[nf>>1][(nf&1)*2+1]);
                    if (dual) {
                        uint32_t bl[2][4];
#pragma unroll
                        for (int tt = 0; tt < 2; tt++)
                            ldsm4t(bl[tt][0], bl[tt][1], bl[tt][2], bl[tt][3],
                                   sptr(&Bs1[s][ks + (lane & 15)][wn*32 + 16*tt + ((lane >> 4) << 3)]));
#pragma unroll
                        for (int mf = 0; mf < 4; mf++)
#pragma unroll
                            for (int nf = 0; nf < 4; nf++)
                                mma16816(acc[mf][nf], af[mf], bl[nf>>1][(nf&1)*2], bl[nf>>1][(nf&1)*2+1]);
                    }
                }
            }
            __syncthreads();
        }
    }

    // ---- epilogue: +bias, relu, store f32 (+ optional bf16 split) ----
#pragma unroll
    for (int nf = 0; nf < 4; nf++) {
        int col = wn*32 + 8*nf + 2*q;
        float b0 = bias[col], b1 = bias[col + 1];
#pragma unroll
        for (int mf = 0; mf < 4; mf++) {
            int row0 = m0 + wm*64 + 16*mf + g;
            float v0 = fmaxf(acc[mf][nf][0] + b0, 0.f);
            float v1 = fmaxf(acc[mf][nf][1] + b1, 0.f);
            float v2 = fmaxf(acc[mf][nf][2] + b0, 0.f);
            float v3 = fmaxf(acc[mf][nf][3] + b1, 0.f);
            *(float2*)&C[(size_t)row0 * 128 + col]       = make_float2(v0, v1);
            *(float2*)&C[(size_t)(row0 + 8) * 128 + col] = make_float2(v2, v3);
            if (Ch) {
                bf16 h0,h1,h2,h3,l0,l1,l2,l3;
                bfsplit(v0,h0,l0); bfsplit(v1,h1,l1); bfsplit(v2,h2,l2); bfsplit(v3,h3,l3);
                *(__nv_bfloat162*)&Ch[(size_t)row0*128 + col]     = __halves2bfloat162(h0,h1);
                *(__nv_bfloat162*)&Ch[(size_t)(row0+8)*128 + col] = __halves2bfloat162(h2,h3);
                *(__nv_bfloat162*)&Cl[(size_t)row0*128 + col]     = __halves2bfloat162(l0,l1);
                *(__nv_bfloat162*)&Cl[(size_t)(row0+8)*128 + col] = __halves2bfloat162(l2,l3);
            }
        }
    }
}

// ---------------- LayerNorm over D=128, one warp per row; emits f32 + bf16 split
__global__ void ln_k(const float* __restrict__ in, const float* __restrict__ gam,
                     const float* __restrict__ bet, float* __restrict__ out)
{
    int wid = threadIdx.x >> 5, lane = threadIdx.x & 31;
    int row = blockIdx.x * 8 + wid;
    const float4* ip = (const float4*)(in + (size_t)row * 128);
    float4 v = ip[lane];
    float s  = v.x + v.y + v.z + v.w;
    float sq = v.x*v.x + v.y*v.y + v.z*v.z + v.w*v.w;
#pragma unroll
    for (int o = 16; o; o >>= 1) {
        s  += __shfl_xor_sync(0xffffffffu, s,  o);
        sq += __shfl_xor_sync(0xffffffffu, sq, o);
    }
    float mu  = s * (1.f/128.f);
    float var = sq * (1.f/128.f) - mu*mu;
    float inv = rsqrtf(var + 1e-5f);
    float4 gg = ((const float4*)gam)[lane];
    float4 bb = ((const float4*)bet)[lane];
    float4 o4;
    o4.x = (v.x - mu)*inv*gg.x + bb.x;
    o4.y = (v.y - mu)*inv*gg.y + bb.y;
    o4.z = (v.z - mu)*inv*gg.z + bb.z;
    o4.w = (v.w - mu)*inv*gg.w + bb.w;
    ((float4*)(out + (size_t)row * 128))[lane] = o4;
    size_t base = (size_t)row * 128 + lane * 4;
    bf16 h0,h1,h2,h3,l0,l1,l2,l3;
    bfsplit(o4.x,h0,l0); bfsplit(o4.y,h1,l1); bfsplit(o4.z,h2,l2); bfsplit(o4.w,h3,l3);
    *(__nv_bfloat162*)&g_lmh[base]   = __halves2bfloat162(h0,h1);
    *(__nv_bfloat162*)&g_lmh[base+2] = __halves2bfloat162(h2,h3);
    *(__nv_bfloat162*)&g_lml[base]   = __halves2bfloat162(l0,l1);
    *(__nv_bfloat162*)&g_lml[base+2] = __halves2bfloat162(l2,l3);
}

// ---------------- edge preprocessing ----------------
__global__ void hist_k(const void* __restrict__ ei, const void* __restrict__ et) {
    int i = blockIdx.x*blockDim.x + threadIdx.x;
    int stride = gridDim.x*blockDim.x;
    for (; i < Ee; i += stride) {
        int dst = load_int(ei, (long long)Ee + i);
        int rel = load_int(et, i);
        atomicAdd(&g_cnt[dst * Rr + rel], 1);
    }
}

__global__ void scan1_k() {
    __shared__ int wsum[32];
    int tid = threadIdx.x, lane = tid & 31, wid = tid >> 5;
    int gidx = blockIdx.x * 1024 + tid;
    int v = g_cnt[gidx];
    int x = v;
#pragma unroll
    for (int o = 1; o < 32; o <<= 1) {
        int t = __shfl_up_sync(0xffffffffu, x, o);
        if (lane >= o) x += t;
    }
    if (lane == 31) wsum[wid] = x;
    __syncthreads();
    if (wid == 0) {
        int w = wsum[lane];
#pragma unroll
        for (int o = 1; o < 32; o <<= 1) {
            int t = __shfl_up_sync(0xffffffffu, w, o);
            if (lane >= o) w += t;
        }
        wsum[lane] = w;
    }
    __syncthreads();
    int incl = x + (wid ? wsum[wid-1] : 0);
    g_off[gidx] = incl - v;
    if (tid == 1023) g_bsum[blockIdx.x] = incl;
}

__global__ void scan2_k() {
    __shared__ int wsum[4];
    int tid = threadIdx.x, lane = tid & 31, wid = tid >> 5;
    int v = (tid < 96) ? g_bsum[tid] : 0;
    int x = v;
#pragma unroll
    for (int o = 1; o < 32; o <<= 1) {
        int t = __shfl_up_sync(0xffffffffu, x, o);
        if (lane >= o) x += t;
    }
    if (lane == 31) wsum[wid] = x;
    __syncthreads();
    int pre = 0;
    for (int w = 0; w < wid; w++) pre += wsum[w];
    int incl = x + pre;
    if (tid < 96) g_bsum[tid] = incl - v;
    if (tid == 95) g_off[NRr] = incl;
}

__global__ void scan3_k() {
    int gidx = blockIdx.x * 1024 + threadIdx.x;
    g_off[gidx] += g_bsum[blockIdx.x];
}

__global__ void scatter_k(const void* __restrict__ ei, const void* __restrict__ et) {
    int i = blockIdx.x*blockDim.x + threadIdx.x;
    int stride = gridDim.x*blockDim.x;
    for (; i < Ee; i += stride) {
        int dst = load_int(ei, (long long)Ee + i);
        int rel = load_int(et, i);
        int src = load_int(ei, i);
        int seg = dst * Rr + rel;
        int pos = g_off[seg] + atomicAdd(&g_cursor[seg], 1);
        g_srcs[pos] = src;
    }
}

// ---------------- per-segment mean aggregation -> bf16 hi/lo, no atomics -----
__global__ void agg_k(const float* __restrict__ x) {
    int warp = blockIdx.x * (blockDim.x >> 5) + (threadIdx.x >> 5);
    if (warp >= NRr) return;
    int lane = threadIdx.x & 31;
    int beg = g_off[warp], end = g_off[warp + 1];
    float a0 = 0.f, a1 = 0.f, a2 = 0.f, a3 = 0.f;
    for (int i = beg; i < end; i++) {
        const float* xr = x + (size_t)g_srcs[i] * 128;
        a0 += xr[lane];       a1 += xr[lane + 32];
        a2 += xr[lane + 64];  a3 += xr[lane + 96];
    }
    int c = end - beg;
    float inv = 1.f / (float)(c > 0 ? c : 1);
    int n = warp / Rr, r = warp % Rr;
    size_t base = (size_t)n * (Rr*Dd) + r * Dd;
    float v; bf16 h, l;
    v = a0*inv; bfsplit(v,h,l); g_aggh[base+lane]    = h; g_aggl[base+lane]    = l;
    v = a1*inv; bfsplit(v,h,l); g_aggh[base+lane+32] = h; g_aggl[base+lane+32] = l;
    v = a2*inv; bfsplit(v,h,l); g_aggh[base+lane+64] = h; g_aggl[base+lane+64] = l;
    v = a3*inv; bfsplit(v,h,l); g_aggh[base+lane+96] = h; g_aggl[base+lane+96] = l;
}

// ---------------- classifier + masked CE; warp per row ----------------
__global__ void cls_k(const float* __restrict__ lm, const float* __restrict__ gx,
                      const float* __restrict__ W, const float* __restrict__ cb,
                      const void* __restrict__ labels, const void* __restrict__ amask,
                      float* __restrict__ logits_out)
{
    __shared__ float s_nll[8];
    __shared__ float s_val[8];
    int wid = threadIdx.x >> 5, lane = threadIdx.x & 31;
    int row = blockIdx.x * 8 + wid;

    float4 f0, f1;
    if (lane < 16) {
        const float* p = lm + (size_t)row * 128 + lane * 8;
        f0 = *(const float4*)p; f1 = *(const float4*)(p + 4);
    } else {
        const float* p = gx + (size_t)row * 128 + (lane - 16) * 8;
        f0 = *(const float4*)p; f1 = *(const float4*)(p + 4);
    }
    float acc[8];
    const float4* W4 = (const float4*)W;
#pragma unroll
    for (int c = 0; c < 8; c++) {
        float4 w0 = W4[c*64 + lane*2];
        float4 w1 = W4[c*64 + lane*2 + 1];
        acc[c] = f0.x*w0.x + f0.y*w0.y + f0.z*w0.z + f0.w*w0.w
               + f1.x*w1.x + f1.y*w1.y + f1.z*w1.z + f1.w*w1.w;
    }
#pragma unroll
    for (int c = 0; c < 8; c++)
#pragma unroll
        for (int o = 16; o; o >>= 1)
            acc[c] += __shfl_xor_sync(0xffffffffu, acc[c], o);

    if (lane == 0) {
        float lg[8];
#pragma unroll
        for (int c = 0; c < 8; c++) lg[c] = acc[c] + cb[c];
        float mx = lg[0];
#pragma unroll
        for (int c = 1; c < 8; c++) mx = fmaxf(mx, lg[c]);
        float se = 0.f;
#pragma unroll
        for (int c = 0; c < 8; c++) se += expf(lg[c] - mx);
        float lse = mx + logf(se);
#pragma unroll
        for (int c = 0; c < 8; c++) logits_out[(size_t)row * 8 + c] = lg[c];
        int lab = load_int(labels, row);
        bool valid = (load_int(amask, row) == 1);
        s_nll[wid] = valid ? (lse - lg[lab]) : 0.f;
        s_val[wid] = valid ? 1.f : 0.f;
    }
    __syncthreads();
    if (threadIdx.x == 0) {
        float sn = 0.f, sv = 0.f;
#pragma unroll
        for (int i = 0; i < 8; i++) { sn += s_nll[i]; sv += s_val[i]; }
        atomicAdd(&g_loss[0], sn);
        atomicAdd(&g_loss[1], sv);
    }
}

__global__ void fin_k(float* __restrict__ out) {
    out[0] = g_loss[0] / fmaxf(g_loss[1], 1.f);
}

// ---------------- launch ----------------
extern "C" void kernel_launch(void* const* d_in, const int* in_sizes, int n_in,
                              void* d_out, int out_size)
{
    const float* outp   = (const float*)d_in[0];
    const void*  ei     = d_in[1];
    const void*  et     = d_in[2];
    const void*  amask  = d_in[3];
    const void*  labels = d_in[4];
    const float* lm_W   = (const float*)d_in[5];
    const float* lm_b   = (const float*)d_in[6];
    const float* ln_g   = (const float*)d_in[7];
    const float* ln_b   = (const float*)d_in[8];
    const float* W_rel  = (const float*)d_in[9];
    const float* W_root = (const float*)d_in[10];
    const float* conv_b = (const float*)d_in[11];
    const float* cls_W  = (const float*)d_in[12];
    const float* cls_b  = (const float*)d_in[13];
    float* out = (float*)d_out;

    static bool attr_set = false;
    if (!attr_set) {
        cudaFuncSetAttribute(gemm3_k, cudaFuncAttributeMaxDynamicSharedMemorySize, GEMM_SMEM_F32);
        attr_set = true;
    }

    void *p_lm, *p_x, *p_x2, *p_lg;
    void *p_Wth, *p_Wtl, *p_aggh, *p_aggl;
    void *p_lmh, *p_lml, *p_xh, *p_xl;
    void *p_Wrelh, *p_Wrell, *p_Wrooth, *p_Wrootl;
    cudaGetSymbolAddress(&p_lm,  g_lm);
    cudaGetSymbolAddress(&p_x,   g_x);
    cudaGetSymbolAddress(&p_x2,  g_x2);
    cudaGetSymbolAddress(&p_lg,  g_logits_scratch);
    cudaGetSymbolAddress(&p_Wth, g_Wth);
    cudaGetSymbolAddress(&p_Wtl, g_Wtl);
    cudaGetSymbolAddress(&p_aggh, g_aggh);
    cudaGetSymbolAddress(&p_aggl, g_aggl);
    cudaGetSymbolAddress(&p_lmh, g_lmh);
    cudaGetSymbolAddress(&p_lml, g_lml);
    cudaGetSymbolAddress(&p_xh,  g_xh);
    cudaGetSymbolAddress(&p_xl,  g_xl);
    cudaGetSymbolAddress(&p_Wrelh, g_Wrelh);
    cudaGetSymbolAddress(&p_Wrell, g_Wrell);
    cudaGetSymbolAddress(&p_Wrooth, g_Wrooth);
    cudaGetSymbolAddress(&p_Wrootl, g_Wrootl);

    float* lm  = (float*)p_lm;
    float* x1  = (float*)p_x;
    float* x2  = (float*)p_x2;
    bf16*  Wth = (bf16*)p_Wth;  bf16* Wtl = (bf16*)p_Wtl;
    bf16*  aggh = (bf16*)p_aggh; bf16* aggl = (bf16*)p_aggl;
    bf16*  lmh = (bf16*)p_lmh;  bf16* lml = (bf16*)p_lml;
    bf16*  xh  = (bf16*)p_xh;   bf16* xl  = (bf16*)p_xl;
    bf16*  Wrelh = (bf16*)p_Wrelh;   bf16* Wrell = (bf16*)p_Wrell;
    bf16*  Wrooth = (bf16*)p_Wrooth; bf16* Wrootl = (bf16*)p_Wrootl;

    // setup (merged) + probe
    probe_k<<<1, 256>>>((const int*)ei);
    setup_k<<<256, 512>>>(lm_W, W_rel, W_root);

    // LM head GEMM: f32 A, split fused into cp.async pipeline
    gemm3_k<<<Nn/128, 256, GEMM_SMEM_F32>>>(outp, nullptr, nullptr, LMD, Wth, Wtl,
                             nullptr, nullptr, 0, nullptr, nullptr,
                             lm_b, x2, nullptr, nullptr);
    ln_k<<<Nn/8, 256>>>(x2, ln_g, ln_b, lm);

    // edge counting sort (two-level scan)
    hist_k<<<512, 256>>>(ei, et);
    scan1_k<<<96, 1024>>>();
    scan2_k<<<1, 128>>>();
    scan3_k<<<96, 1024>>>();
    scatter_k<<<512, 256>>>(ei, et);

    // layer 0
    agg_k<<<NRr/8, 256>>>(lm);
    gemm3_k<<<Nn/128, 256, GEMM_SMEM_BF16>>>(nullptr, aggh, aggl, Rr*Dd, Wrelh, Wrell,
                             lmh, lml, Dd, Wrooth, Wrootl,
                             conv_b, x1, xh, xl);
    // layer 1
    agg_k<<<NRr/8, 256>>>(x1);
    gemm3_k<<<Nn/128, 256, GEMM_SMEM_BF16>>>(nullptr, aggh, aggl, Rr*Dd, Wrelh + Rr*Dd*Dd, Wrell + Rr*Dd*Dd,
                             xh, xl, Dd, Wrooth + Dd*Dd, Wrootl + Dd*Dd,
                             conv_b + Dd, x2, nullptr, nullptr);

    // classifier + loss
    const int LOGITS = Nn * Cc;
    if (out_size >= LOGITS + 1) {
        cls_k<<<Nn/8, 256>>>(lm, x2, cls_W, cls_b, labels, amask, out + 1);
        fin_k<<<1, 1>>>(out);
    } else if (out_size >= LOGITS) {
        cls_k<<<Nn/8, 256>>>(lm, x2, cls_W, cls_b, labels, amask, out);
    } else {
        cls_k<<<Nn/8, 256>>>(lm, x2, cls_W, cls_b, labels, amask, (float*)p_lg);
        fin_k<<<1, 1>>>(out);
    }
}

// round 15
// speedup vs baseline: 1.5854x; 1.0498x over previous
#include <cuda_runtime.h>
#include <cuda_bf16.h>
#include <cstdint>

#define Bb 32
#define Ll 1024
#define LMD 1024
#define Dd 128
#define Rr 3
#define NLAYERS 2
#define Cc 8
#define Nn (Bb*Ll)          // 32768
#define Ee 524288
#define NRr (Nn*Rr)         // 98304

typedef __nv_bfloat16 bf16;

// ---------------- scratch (device globals; no allocations allowed) ----------
__device__ float g_lm[Nn*Dd];
__device__ bf16  g_lmh[Nn*Dd], g_lml[Nn*Dd];
__device__ float g_x[Nn*Dd];
__device__ bf16  g_xh[Nn*Dd], g_xl[Nn*Dd];
__device__ float g_x2[Nn*Dd];
__device__ bf16  g_aggh[(size_t)Nn*Rr*Dd], g_aggl[(size_t)Nn*Rr*Dd];
__device__ bf16  g_Wth[LMD*Dd], g_Wtl[LMD*Dd];
__device__ bf16  g_Wrelh[NLAYERS*Rr*Dd*Dd], g_Wrell[NLAYERS*Rr*Dd*Dd];
__device__ bf16  g_Wrooth[NLAYERS*Dd*Dd], g_Wrootl[NLAYERS*Dd*Dd];
__device__ float g_logits_scratch[Nn*Cc];
__device__ int   g_cnt[NRr];
__device__ int   g_cursor[NRr];
__device__ int   g_off[NRr+1];
__device__ int   g_bsum[128];
__device__ int   g_srcs[Ee];
__device__ float g_loss[2];
__device__ int   g_is64;

// ---------------- small helpers ----------------
__device__ __forceinline__ uint32_t sptr(const void* p) {
    return (uint32_t)__cvta_generic_to_shared(p);
}
__device__ __forceinline__ void bfsplit(float v, bf16& h, bf16& l) {
    h = __float2bfloat16(v);
    l = __float2bfloat16(v - __bfloat162float(h));
}
__device__ __forceinline__ void cpasync16(uint32_t dst, const void* src) {
    asm volatile("cp.async.cg.shared.global [%0], [%1], 16;" :: "r"(dst), "l"(src));
}
#define CP_COMMIT() asm volatile("cp.async.commit_group;")
#define CP_WAIT0()  asm volatile("cp.async.wait_group 0;")

__device__ __forceinline__ void ldsm4(uint32_t& r0, uint32_t& r1, uint32_t& r2, uint32_t& r3,
                                      uint32_t addr) {
    asm volatile("ldmatrix.sync.aligned.m8n8.x4.shared.b16 {%0,%1,%2,%3}, [%4];"
                 : "=r"(r0), "=r"(r1), "=r"(r2), "=r"(r3) : "r"(addr));
}
__device__ __forceinline__ void ldsm4t(uint32_t& r0, uint32_t& r1, uint32_t& r2, uint32_t& r3,
                                       uint32_t addr) {
    asm volatile("ldmatrix.sync.aligned.m8n8.x4.trans.shared.b16 {%0,%1,%2,%3}, [%4];"
                 : "=r"(r0), "=r"(r1), "=r"(r2), "=r"(r3) : "r"(addr));
}
__device__ __forceinline__ void mma16816(float* c, const uint32_t* a, uint32_t b0, uint32_t b1) {
    asm volatile("mma.sync.aligned.m16n8k16.row.col.f32.bf16.bf16.f32 "
                 "{%0,%1,%2,%3},{%4,%5,%6,%7},{%8,%9},{%0,%1,%2,%3};"
                 : "+f"(c[0]), "+f"(c[1]), "+f"(c[2]), "+f"(c[3])
                 : "r"(a[0]), "r"(a[1]), "r"(a[2]), "r"(a[3]), "r"(b0), "r"(b1));
}

// ---------------- int dtype probe ----------------
__global__ void probe_k(const int* __restrict__ p) {
    __shared__ int bad;
    if (threadIdx.x == 0) bad = 0;
    __syncthreads();
    for (int i = threadIdx.x; i < 1024; i += blockDim.x)
        if (p[2*i + 1] != 0) bad = 1;
    __syncthreads();
    if (threadIdx.x == 0) g_is64 = bad ? 0 : 1;
}
__device__ __forceinline__ int load_int(const void* p, long long idx) {
    if (g_is64) return (int)((const long long*)p)[idx];
    return ((const int*)p)[idx];
}

// ---------------- merged setup: zero + transW split + W_rel/W_root splits ----
__global__ void setup_k(const float* __restrict__ lm_W,
                        const float* __restrict__ W_rel,
                        const float* __restrict__ W_root) {
    int i = blockIdx.x*blockDim.x + threadIdx.x;
    int stride = gridDim.x*blockDim.x;
    for (; i < LMD*Dd; i += stride) {
        if (i < NRr) { g_cnt[i] = 0; g_cursor[i] = 0; }
        {
            int k = i >> 7, h = i & 127;
            float v = lm_W[h*LMD + k];
            bf16 hi, lo; bfsplit(v, hi, lo);
            g_Wth[i] = hi; g_Wtl[i] = lo;
        }
        if (i < NLAYERS*Rr*Dd*Dd) {
            bf16 hi, lo; bfsplit(W_rel[i], hi, lo);
            g_Wrelh[i] = hi; g_Wrell[i] = lo;
        }
        if (i < NLAYERS*Dd*Dd) {
            bf16 hi, lo; bfsplit(W_root[i], hi, lo);
            g_Wrooth[i] = hi; g_Wrootl[i] = lo;
        }
        if (i < 2) g_loss[i] = 0.f;
    }
}

// ---------------- tensor-core GEMM, 3xBF16 split, cp.async 2-stage pipeline --
#define GEMM_SMEM_BF16 (2*128*40*2 + 2*32*136*2 + 2*32*136*2)               // 55296
#define GEMM_SMEM_F32  (2*128*36*4 + 128*40*2 + 128*40*2 + 2*32*136*2*2)    // 92160

__global__ __launch_bounds__(256, 2)
void gemm3_k(const float* __restrict__ A1f,
             const bf16* __restrict__ A1h, const bf16* __restrict__ A1l, int K1,
             const bf16* __restrict__ B1h, const bf16* __restrict__ B1l,
             const bf16* __restrict__ A2h, const bf16* __restrict__ A2l, int K2,
             const bf16* __restrict__ B2h, const bf16* __restrict__ B2l,
             const float* __restrict__ bias, float* __restrict__ C,
             bf16* __restrict__ Ch, bf16* __restrict__ Cl)
{
    extern __shared__ bf16 smem[];

    const int tid  = threadIdx.x;
    const int wid  = tid >> 5;
    const int lane = tid & 31;
    const int wm   = wid >> 2;
    const int wn   = wid & 3;
    const int m0   = blockIdx.x * 128;
    const int g    = lane >> 2;
    const int q    = lane & 3;

    const int b_row0 = tid >> 4, b_cc = (tid & 15) * 8;

    float acc[4][4][4];
#pragma unroll
    for (int i = 0; i < 4; i++)
#pragma unroll
        for (int j = 0; j < 4; j++)
#pragma unroll
            for (int r = 0; r < 4; r++) acc[i][j][r] = 0.f;

    if (A1f) {
        // ---------------- f32-A mode (LM head) ----------------
        float (*Af32)[128][36] = (float(*)[128][36])(smem);
        bf16  (*Ash)[40]       = (bf16(*)[40])(smem + 2*128*36*2);
        bf16  (*Asl)[40]       = (bf16(*)[40])(smem + 2*128*36*2 + 128*40);
        bf16  (*Bs0)[32][136]  = (bf16(*)[32][136])(smem + 2*128*36*2 + 2*128*40);
        bf16  (*Bs1)[32][136]  = (bf16(*)[32][136])(smem + 2*128*36*2 + 2*128*40 + 2*32*136);

        const int K = K1;
        const int T = K >> 5;
        const int af_row = tid >> 3, af_cc = (tid & 7) * 4;

        {
#pragma unroll
            for (int r = 0; r < 4; r++)
                cpasync16(sptr(&Af32[0][af_row + 32*r][af_cc]),
                          A1f + (size_t)(m0 + af_row + 32*r) * K + af_cc);
            cpasync16(sptr(&Bs0[0][b_row0][b_cc]),      B1h + (size_t)b_row0 * 128 + b_cc);
            cpasync16(sptr(&Bs0[0][b_row0 + 16][b_cc]), B1h + (size_t)(b_row0 + 16) * 128 + b_cc);
            cpasync16(sptr(&Bs1[0][b_row0][b_cc]),      B1l + (size_t)b_row0 * 128 + b_cc);
            cpasync16(sptr(&Bs1[0][b_row0 + 16][b_cc]), B1l + (size_t)(b_row0 + 16) * 128 + b_cc);
            CP_COMMIT();
        }

#pragma unroll 1
        for (int t = 0; t < T; t++) {
            CP_WAIT0();
            __syncthreads();
            const int s = t & 1;
            if (t + 1 < T) {
                const int ns = s ^ 1;
                const int kt = (t + 1) << 5;
#pragma unroll
                for (int r = 0; r < 4; r++)
                    cpasync16(sptr(&Af32[ns][af_row + 32*r][af_cc]),
                              A1f + (size_t)(m0 + af_row + 32*r) * K + kt + af_cc);
                cpasync16(sptr(&Bs0[ns][b_row0][b_cc]),      B1h + (size_t)(kt + b_row0) * 128 + b_cc);
                cpasync16(sptr(&Bs0[ns][b_row0 + 16][b_cc]), B1h + (size_t)(kt + b_row0 + 16) * 128 + b_cc);
                cpasync16(sptr(&Bs1[ns][b_row0][b_cc]),      B1l + (size_t)(kt + b_row0) * 128 + b_cc);
                cpasync16(sptr(&Bs1[ns][b_row0 + 16][b_cc]), B1l + (size_t)(kt + b_row0 + 16) * 128 + b_cc);
                CP_COMMIT();
            }
#pragma unroll
            for (int r = 0; r < 4; r++) {
                int row = af_row + 32*r;
                float4 v = *(float4*)&Af32[s][row][af_cc];
                bf16 h0,h1,h2,h3,l0,l1,l2,l3;
                bfsplit(v.x,h0,l0); bfsplit(v.y,h1,l1); bfsplit(v.z,h2,l2); bfsplit(v.w,h3,l3);
                *(__nv_bfloat162*)&Ash[row][af_cc]     = __halves2bfloat162(h0,h1);
                *(__nv_bfloat162*)&Ash[row][af_cc + 2] = __halves2bfloat162(h2,h3);
                *(__nv_bfloat162*)&Asl[row][af_cc]     = __halves2bfloat162(l0,l1);
                *(__nv_bfloat162*)&Asl[row][af_cc + 2] = __halves2bfloat162(l2,l3);
            }
            __syncthreads();

#pragma unroll
            for (int ks = 0; ks < 32; ks += 16) {
                uint32_t af[4][4];
#pragma unroll
                for (int f = 0; f < 4; f++)
                    ldsm4(af[f][0], af[f][1], af[f][2], af[f][3],
                          sptr(&Ash[wm*64 + 16*f + (lane & 15)][ks + ((lane >> 4) << 3)]));
                uint32_t bh[2][4], bl[2][4];
#pragma unroll
                for (int tt = 0; tt < 2; tt++) {
                    ldsm4t(bh[tt][0], bh[tt][1], bh[tt][2], bh[tt][3],
                           sptr(&Bs0[s][ks + (lane & 15)][wn*32 + 16*tt + ((lane >> 4) << 3)]));
                    ldsm4t(bl[tt][0], bl[tt][1], bl[tt][2], bl[tt][3],
                           sptr(&Bs1[s][ks + (lane & 15)][wn*32 + 16*tt + ((lane >> 4) << 3)]));
                }
#pragma unroll
                for (int mf = 0; mf < 4; mf++)
#pragma unroll
                    for (int nf = 0; nf < 4; nf++) {
                        mma16816(acc[mf][nf], af[mf], bh[nf>>1][(nf&1)*2], bh[nf>>1][(nf&1)*2+1]);
                        mma16816(acc[mf][nf], af[mf], bl[nf>>1][(nf&1)*2], bl[nf>>1][(nf&1)*2+1]);
                    }
#pragma unroll
                for (int f = 0; f < 4; f++)
                    ldsm4(af[f][0], af[f][1], af[f][2], af[f][3],
                          sptr(&Asl[wm*64 + 16*f + (lane & 15)][ks + ((lane >> 4) << 3)]));
#pragma unroll
                for (int mf = 0; mf < 4; mf++)
#pragma unroll
                    for (int nf = 0; nf < 4; nf++)
                        mma16816(acc[mf][nf], af[mf], bh[nf>>1][(nf&1)*2], bh[nf>>1][(nf&1)*2+1]);
            }
        }
    } else {
        // ---------------- pre-split bf16 mode, 4 passes ----------------
        bf16 (*As)[128][40]  = (bf16(*)[128][40])(smem);
        bf16 (*Bs0)[32][136] = (bf16(*)[32][136])(smem + 2*128*40);
        bf16 (*Bs1)[32][136] = (bf16(*)[32][136])(smem + 2*128*40 + 2*32*136);
        const int a_row0 = tid >> 2, a_cc = (tid & 3) * 8;

#pragma unroll 1
        for (int pass = 0; pass < 4; pass++) {
            const bf16* Ap; const bf16* Bp0; const bf16* Bp1; int K;
            if      (pass == 0) { Ap = A1h; Bp0 = B1h; Bp1 = B1l; K = K1; }
            else if (pass == 1) { Ap = A1l; Bp0 = B1h; Bp1 = nullptr; K = K1; }
            else if (pass == 2) { Ap = A2h; Bp0 = B2h; Bp1 = B2l; K = K2; }
            else                { Ap = A2l; Bp0 = B2h; Bp1 = nullptr; K = K2; }
            if (Ap == nullptr || K == 0) continue;
            const bool dual = (Bp1 != nullptr);
            const int T = K >> 5;

            {
                cpasync16(sptr(&As[0][a_row0][a_cc]),      Ap + (size_t)(m0 + a_row0) * K + a_cc);
                cpasync16(sptr(&As[0][a_row0 + 64][a_cc]), Ap + (size_t)(m0 + a_row0 + 64) * K + a_cc);
                cpasync16(sptr(&Bs0[0][b_row0][b_cc]),      Bp0 + (size_t)b_row0 * 128 + b_cc);
                cpasync16(sptr(&Bs0[0][b_row0 + 16][b_cc]), Bp0 + (size_t)(b_row0 + 16) * 128 + b_cc);
                if (dual) {
                    cpasync16(sptr(&Bs1[0][b_row0][b_cc]),      Bp1 + (size_t)b_row0 * 128 + b_cc);
                    cpasync16(sptr(&Bs1[0][b_row0 + 16][b_cc]), Bp1 + (size_t)(b_row0 + 16) * 128 + b_cc);
                }
                CP_COMMIT();
            }

#pragma unroll 1
            for (int t = 0; t < T; t++) {
                CP_WAIT0();
                __syncthreads();
                const int s = t & 1;
                if (t + 1 < T) {
                    const int ns = s ^ 1;
                    const int kt = (t + 1) << 5;
                    cpasync16(sptr(&As[ns][a_row0][a_cc]),      Ap + (size_t)(m0 + a_row0) * K + kt + a_cc);
                    cpasync16(sptr(&As[ns][a_row0 + 64][a_cc]), Ap + (size_t)(m0 + a_row0 + 64) * K + kt + a_cc);
                    cpasync16(sptr(&Bs0[ns][b_row0][b_cc]),      Bp0 + (size_t)(kt + b_row0) * 128 + b_cc);
                    cpasync16(sptr(&Bs0[ns][b_row0 + 16][b_cc]), Bp0 + (size_t)(kt + b_row0 + 16) * 128 + b_cc);
                    if (dual) {
                        cpasync16(sptr(&Bs1[ns][b_row0][b_cc]),      Bp1 + (size_t)(kt + b_row0) * 128 + b_cc);
                        cpasync16(sptr(&Bs1[ns][b_row0 + 16][b_cc]), Bp1 + (size_t)(kt + b_row0 + 16) * 128 + b_cc);
                    }
                    CP_COMMIT();
                }

#pragma unroll
                for (int ks = 0; ks < 32; ks += 16) {
                    uint32_t af[4][4];
#pragma unroll
                    for (int f = 0; f < 4; f++)
                        ldsm4(af[f][0], af[f][1], af[f][2], af[f][3],
                              sptr(&As[s][wm*64 + 16*f + (lane & 15)][ks + ((lane >> 4) << 3)]));
                    uint32_t bh[2][4];
#pragma unroll
                    for (int tt = 0; tt < 2; tt++)
                        ldsm4t(bh[tt][0], bh[tt][1], bh[tt][2], bh[tt][3],
                               sptr(&Bs0[s][ks + (lane & 15)][wn*32 + 16*tt + ((lane >> 4) << 3)]));
#pragma unroll
                    for (int mf = 0; mf < 4; mf++)
#pragma unroll
                        for (int nf = 0; nf < 4; nf++)
                            mma16816(acc[mf][nf], af[mf], bh[nf>>1][(nf&1)*2], bh[nf>>1][(nf&1)*2+1]);
                    if (dual) {
                        uint32_t bl[2][4];
#pragma unroll
                        for (int tt = 0; tt < 2; tt++)
                            ldsm4t(bl[tt][0], bl[tt][1], bl[tt][2], bl[tt][3],
                                   sptr(&Bs1[s][ks + (lane & 15)][wn*32 + 16*tt + ((lane >> 4) << 3)]));
#pragma unroll
                        for (int mf = 0; mf < 4; mf++)
#pragma unroll
                            for (int nf = 0; nf < 4; nf++)
                                mma16816(acc[mf][nf], af[mf], bl[nf>>1][(nf&1)*2], bl[nf>>1][(nf&1)*2+1]);
                    }
                }
            }
            __syncthreads();
        }
    }

    // ---- epilogue ----
#pragma unroll
    for (int nf = 0; nf < 4; nf++) {
        int col = wn*32 + 8*nf + 2*q;
        float b0 = bias[col], b1 = bias[col + 1];
#pragma unroll
        for (int mf = 0; mf < 4; mf++) {
            int row0 = m0 + wm*64 + 16*mf + g;
            float v0 = fmaxf(acc[mf][nf][0] + b0, 0.f);
            float v1 = fmaxf(acc[mf][nf][1] + b1, 0.f);
            float v2 = fmaxf(acc[mf][nf][2] + b0, 0.f);
            float v3 = fmaxf(acc[mf][nf][3] + b1, 0.f);
            *(float2*)&C[(size_t)row0 * 128 + col]       = make_float2(v0, v1);
            *(float2*)&C[(size_t)(row0 + 8) * 128 + col] = make_float2(v2, v3);
            if (Ch) {
                bf16 h0,h1,h2,h3,l0,l1,l2,l3;
                bfsplit(v0,h0,l0); bfsplit(v1,h1,l1); bfsplit(v2,h2,l2); bfsplit(v3,h3,l3);
                *(__nv_bfloat162*)&Ch[(size_t)row0*128 + col]     = __halves2bfloat162(h0,h1);
                *(__nv_bfloat162*)&Ch[(size_t)(row0+8)*128 + col] = __halves2bfloat162(h2,h3);
                *(__nv_bfloat162*)&Cl[(size_t)row0*128 + col]     = __halves2bfloat162(l0,l1);
                *(__nv_bfloat162*)&Cl[(size_t)(row0+8)*128 + col] = __halves2bfloat162(l2,l3);
            }
        }
    }
}

// ---------------- LayerNorm ----------------
__global__ void ln_k(const float* __restrict__ in, const float* __restrict__ gam,
                     const float* __restrict__ bet, float* __restrict__ out)
{
    int wid = threadIdx.x >> 5, lane = threadIdx.x & 31;
    int row = blockIdx.x * 8 + wid;
    const float4* ip = (const float4*)(in + (size_t)row * 128);
    float4 v = ip[lane];
    float s  = v.x + v.y + v.z + v.w;
    float sq = v.x*v.x + v.y*v.y + v.z*v.z + v.w*v.w;
#pragma unroll
    for (int o = 16; o; o >>= 1) {
        s  += __shfl_xor_sync(0xffffffffu, s,  o);
        sq += __shfl_xor_sync(0xffffffffu, sq, o);
    }
    float mu  = s * (1.f/128.f);
    float var = sq * (1.f/128.f) - mu*mu;
    float inv = rsqrtf(var + 1e-5f);
    float4 gg = ((const float4*)gam)[lane];
    float4 bb = ((const float4*)bet)[lane];
    float4 o4;
    o4.x = (v.x - mu)*inv*gg.x + bb.x;
    o4.y = (v.y - mu)*inv*gg.y + bb.y;
    o4.z = (v.z - mu)*inv*gg.z + bb.z;
    o4.w = (v.w - mu)*inv*gg.w + bb.w;
    ((float4*)(out + (size_t)row * 128))[lane] = o4;
    size_t base = (size_t)row * 128 + lane * 4;
    bf16 h0,h1,h2,h3,l0,l1,l2,l3;
    bfsplit(o4.x,h0,l0); bfsplit(o4.y,h1,l1); bfsplit(o4.z,h2,l2); bfsplit(o4.w,h3,l3);
    *(__nv_bfloat162*)&g_lmh[base]   = __halves2bfloat162(h0,h1);
    *(__nv_bfloat162*)&g_lmh[base+2] = __halves2bfloat162(h2,h3);
    *(__nv_bfloat162*)&g_lml[base]   = __halves2bfloat162(l0,l1);
    *(__nv_bfloat162*)&g_lml[base+2] = __halves2bfloat162(l2,l3);
}

// ---------------- edge preprocessing ----------------
__global__ void hist_k(const void* __restrict__ ei, const void* __restrict__ et) {
    int i = blockIdx.x*blockDim.x + threadIdx.x;
    int stride = gridDim.x*blockDim.x;
    for (; i < Ee; i += stride) {
        int dst = load_int(ei, (long long)Ee + i);
        int rel = load_int(et, i);
        atomicAdd(&g_cnt[dst * Rr + rel], 1);
    }
}

__global__ void scan1_k() {
    __shared__ int wsum[32];
    int tid = threadIdx.x, lane = tid & 31, wid = tid >> 5;
    int gidx = blockIdx.x * 1024 + tid;
    int v = g_cnt[gidx];
    int x = v;
#pragma unroll
    for (int o = 1; o < 32; o <<= 1) {
        int t = __shfl_up_sync(0xffffffffu, x, o);
        if (lane >= o) x += t;
    }
    if (lane == 31) wsum[wid] = x;
    __syncthreads();
    if (wid == 0) {
        int w = wsum[lane];
#pragma unroll
        for (int o = 1; o < 32; o <<= 1) {
            int t = __shfl_up_sync(0xffffffffu, w, o);
            if (lane >= o) w += t;
        }
        wsum[lane] = w;
    }
    __syncthreads();
    int incl = x + (wid ? wsum[wid-1] : 0);
    g_off[gidx] = incl - v;
    if (tid == 1023) g_bsum[blockIdx.x] = incl;
}

__global__ void scan2_k() {
    __shared__ int wsum[4];
    int tid = threadIdx.x, lane = tid & 31, wid = tid >> 5;
    int v = (tid < 96) ? g_bsum[tid] : 0;
    int x = v;
#pragma unroll
    for (int o = 1; o < 32; o <<= 1) {
        int t = __shfl_up_sync(0xffffffffu, x, o);
        if (lane >= o) x += t;
    }
    if (lane == 31) wsum[wid] = x;
    __syncthreads();
    int pre = 0;
    for (int w = 0; w < wid; w++) pre += wsum[w];
    int incl = x + pre;
    if (tid < 96) g_bsum[tid] = incl - v;
    if (tid == 95) g_off[NRr] = incl;
}

__global__ void scan3_k() {
    int gidx = blockIdx.x * 1024 + threadIdx.x;
    g_off[gidx] += g_bsum[blockIdx.x];
}

__global__ void scatter_k(const void* __restrict__ ei, const void* __restrict__ et) {
    int i = blockIdx.x*blockDim.x + threadIdx.x;
    int stride = gridDim.x*blockDim.x;
    for (; i < Ee; i += stride) {
        int dst = load_int(ei, (long long)Ee + i);
        int rel = load_int(et, i);
        int src = load_int(ei, i);
        int seg = dst * Rr + rel;
        int pos = g_off[seg] + atomicAdd(&g_cursor[seg], 1);
        g_srcs[pos] = src;
    }
}

// ---------------- per-segment mean aggregation (float4 loads) ----------------
__global__ void agg_k(const float* __restrict__ x) {
    int warp = blockIdx.x * (blockDim.x >> 5) + (threadIdx.x >> 5);
    if (warp >= NRr) return;
    int lane = threadIdx.x & 31;
    int beg = g_off[warp], end = g_off[warp + 1];
    float4 a = make_float4(0.f, 0.f, 0.f, 0.f);
    for (int i = beg; i < end; i++) {
        const float4* xr = (const float4*)(x + (size_t)g_srcs[i] * 128);
        float4 v = xr[lane];
        a.x += v.x; a.y += v.y; a.z += v.z; a.w += v.w;
    }
    int c = end - beg;
    float inv = 1.f / (float)(c > 0 ? c : 1);
    int n = warp / Rr, r = warp % Rr;
    size_t base = (size_t)n * (Rr*Dd) + r * Dd + lane * 4;
    bf16 h0,h1,h2,h3,l0,l1,l2,l3;
    bfsplit(a.x*inv,h0,l0); bfsplit(a.y*inv,h1,l1);
    bfsplit(a.z*inv,h2,l2); bfsplit(a.w*inv,h3,l3);
    *(__nv_bfloat162*)&g_aggh[base]   = __halves2bfloat162(h0,h1);
    *(__nv_bfloat162*)&g_aggh[base+2] = __halves2bfloat162(h2,h3);
    *(__nv_bfloat162*)&g_aggl[base]   = __halves2bfloat162(l0,l1);
    *(__nv_bfloat162*)&g_aggl[base+2] = __halves2bfloat162(l2,l3);
}

// ---------------- classifier + masked CE ----------------
__global__ void cls_k(const float* __restrict__ lm, const float* __restrict__ gx,
                      const float* __restrict__ W, const float* __restrict__ cb,
                      const void* __restrict__ labels, const void* __restrict__ amask,
                      float* __restrict__ logits_out)
{
    __shared__ float s_nll[8];
    __shared__ float s_val[8];
    int wid = threadIdx.x >> 5, lane = threadIdx.x & 31;
    int row = blockIdx.x * 8 + wid;

    float4 f0, f1;
    if (lane < 16) {
        const float* p = lm + (size_t)row * 128 + lane * 8;
        f0 = *(const float4*)p; f1 = *(const float4*)(p + 4);
    } else {
        const float* p = gx + (size_t)row * 128 + (lane - 16) * 8;
        f0 = *(const float4*)p; f1 = *(const float4*)(p + 4);
    }
    float acc[8];
    const float4* W4 = (const float4*)W;
#pragma unroll
    for (int c = 0; c < 8; c++) {
        float4 w0 = W4[c*64 + lane*2];
        float4 w1 = W4[c*64 + lane*2 + 1];
        acc[c] = f0.x*w0.x + f0.y*w0.y + f0.z*w0.z + f0.w*w0.w
               + f1.x*w1.x + f1.y*w1.y + f1.z*w1.z + f1.w*w1.w;
    }
#pragma unroll
    for (int c = 0; c < 8; c++)
#pragma unroll
        for (int o = 16; o; o >>= 1)
            acc[c] += __shfl_xor_sync(0xffffffffu, acc[c], o);

    if (lane == 0) {
        float lg[8];
#pragma unroll
        for (int c = 0; c < 8; c++) lg[c] = acc[c] + cb[c];
        float mx = lg[0];
#pragma unroll
        for (int c = 1; c < 8; c++) mx = fmaxf(mx, lg[c]);
        float se = 0.f;
#pragma unroll
        for (int c = 0; c < 8; c++) se += expf(lg[c] - mx);
        float lse = mx + logf(se);
#pragma unroll
        for (int c = 0; c < 8; c++) logits_out[(size_t)row * 8 + c] = lg[c];
        int lab = load_int(labels, row);
        bool valid = (load_int(amask, row) == 1);
        s_nll[wid] = valid ? (lse - lg[lab]) : 0.f;
        s_val[wid] = valid ? 1.f : 0.f;
    }
    __syncthreads();
    if (threadIdx.x == 0) {
        float sn = 0.f, sv = 0.f;
#pragma unroll
        for (int i = 0; i < 8; i++) { sn += s_nll[i]; sv += s_val[i]; }
        atomicAdd(&g_loss[0], sn);
        atomicAdd(&g_loss[1], sv);
    }
}

__global__ void fin_k(float* __restrict__ out) {
    out[0] = g_loss[0] / fmaxf(g_loss[1], 1.f);
}

// ---------------- launch ----------------
extern "C" void kernel_launch(void* const* d_in, const int* in_sizes, int n_in,
                              void* d_out, int out_size)
{
    const float* outp   = (const float*)d_in[0];
    const void*  ei     = d_in[1];
    const void*  et     = d_in[2];
    const void*  amask  = d_in[3];
    const void*  labels = d_in[4];
    const float* lm_W   = (const float*)d_in[5];
    const float* lm_b   = (const float*)d_in[6];
    const float* ln_g   = (const float*)d_in[7];
    const float* ln_b   = (const float*)d_in[8];
    const float* W_rel  = (const float*)d_in[9];
    const float* W_root = (const float*)d_in[10];
    const float* conv_b = (const float*)d_in[11];
    const float* cls_W  = (const float*)d_in[12];
    const float* cls_b  = (const float*)d_in[13];
    float* out = (float*)d_out;

    static bool init_done = false;
    static cudaStream_t s2;
    static cudaEvent_t evFork, evJoin;
    if (!init_done) {
        cudaFuncSetAttribute(gemm3_k, cudaFuncAttributeMaxDynamicSharedMemorySize, GEMM_SMEM_F32);
        cudaStreamCreateWithFlags(&s2, cudaStreamNonBlocking);
        cudaEventCreateWithFlags(&evFork, cudaEventDisableTiming);
        cudaEventCreateWithFlags(&evJoin, cudaEventDisableTiming);
        init_done = true;
    }

    void *p_lm, *p_x, *p_x2, *p_lg;
    void *p_Wth, *p_Wtl, *p_aggh, *p_aggl;
    void *p_lmh, *p_lml, *p_xh, *p_xl;
    void *p_Wrelh, *p_Wrell, *p_Wrooth, *p_Wrootl;
    cudaGetSymbolAddress(&p_lm,  g_lm);
    cudaGetSymbolAddress(&p_x,   g_x);
    cudaGetSymbolAddress(&p_x2,  g_x2);
    cudaGetSymbolAddress(&p_lg,  g_logits_scratch);
    cudaGetSymbolAddress(&p_Wth, g_Wth);
    cudaGetSymbolAddress(&p_Wtl, g_Wtl);
    cudaGetSymbolAddress(&p_aggh, g_aggh);
    cudaGetSymbolAddress(&p_aggl, g_aggl);
    cudaGetSymbolAddress(&p_lmh, g_lmh);
    cudaGetSymbolAddress(&p_lml, g_lml);
    cudaGetSymbolAddress(&p_xh,  g_xh);
    cudaGetSymbolAddress(&p_xl,  g_xl);
    cudaGetSymbolAddress(&p_Wrelh, g_Wrelh);
    cudaGetSymbolAddress(&p_Wrell, g_Wrell);
    cudaGetSymbolAddress(&p_Wrooth, g_Wrooth);
    cudaGetSymbolAddress(&p_Wrootl, g_Wrootl);

    float* lm  = (float*)p_lm;
    float* x1  = (float*)p_x;
    float* x2  = (float*)p_x2;
    bf16*  Wth = (bf16*)p_Wth;  bf16* Wtl = (bf16*)p_Wtl;
    bf16*  aggh = (bf16*)p_aggh; bf16* aggl = (bf16*)p_aggl;
    bf16*  lmh = (bf16*)p_lmh;  bf16* lml = (bf16*)p_lml;
    bf16*  xh  = (bf16*)p_xh;   bf16* xl  = (bf16*)p_xl;
    bf16*  Wrelh = (bf16*)p_Wrelh;   bf16* Wrell = (bf16*)p_Wrell;
    bf16*  Wrooth = (bf16*)p_Wrooth; bf16* Wrootl = (bf16*)p_Wrootl;

    // setup (both branches depend on probe + setup)
    probe_k<<<1, 256>>>((const int*)ei);
    setup_k<<<256, 512>>>(lm_W, W_rel, W_root);

    // fork: edge counting sort on s2, concurrent with LM head GEMM + LN
    cudaEventRecord(evFork, 0);
    cudaStreamWaitEvent(s2, evFork, 0);
    hist_k<<<512, 256, 0, s2>>>(ei, et);
    scan1_k<<<96, 1024, 0, s2>>>();
    scan2_k<<<1, 128, 0, s2>>>();
    scan3_k<<<96, 1024, 0, s2>>>();
    scatter_k<<<512, 256, 0, s2>>>(ei, et);
    cudaEventRecord(evJoin, s2);

    // main stream: LM head GEMM (f32 A, fused split) + LN
    gemm3_k<<<Nn/128, 256, GEMM_SMEM_F32>>>(outp, nullptr, nullptr, LMD, Wth, Wtl,
                             nullptr, nullptr, 0, nullptr, nullptr,
                             lm_b, x2, nullptr, nullptr);
    ln_k<<<Nn/8, 256>>>(x2, ln_g, ln_b, lm);

    // join before aggregation needs g_off/g_srcs
    cudaStreamWaitEvent(0, evJoin, 0);

    // layer 0
    agg_k<<<NRr/8, 256>>>(lm);
    gemm3_k<<<Nn/128, 256, GEMM_SMEM_BF16>>>(nullptr, aggh, aggl, Rr*Dd, Wrelh, Wrell,
                             lmh, lml, Dd, Wrooth, Wrootl,
                             conv_b, x1, xh, xl);
    // layer 1
    agg_k<<<NRr/8, 256>>>(x1);
    gemm3_k<<<Nn/128, 256, GEMM_SMEM_BF16>>>(nullptr, aggh, aggl, Rr*Dd, Wrelh + Rr*Dd*Dd, Wrell + Rr*Dd*Dd,
                             xh, xl, Dd, Wrooth + Dd*Dd, Wrootl + Dd*Dd,
                             conv_b + Dd, x2, nullptr, nullptr);

    // classifier + loss
    const int LOGITS = Nn * Cc;
    if (out_size >= LOGITS + 1) {
        cls_k<<<Nn/8, 256>>>(lm, x2, cls_W, cls_b, labels, amask, out + 1);
        fin_k<<<1, 1>>>(out);
    } else if (out_size >= LOGITS) {
        cls_k<<<Nn/8, 256>>>(lm, x2, cls_W, cls_b, labels, amask, out);
    } else {
        cls_k<<<Nn/8, 256>>>(lm, x2, cls_W, cls_b, labels, amask, (float*)p_lg);
        fin_k<<<1, 1>>>(out);
    }
}

// round 17
// speedup vs baseline: 1.6255x; 1.0253x over previous
#include <cuda_runtime.h>
#include <cuda_bf16.h>
#include <cstdint>

#define Bb 32
#define Ll 1024
#define LMD 1024
#define Dd 128
#define Rr 3
#define NLAYERS 2
#define Cc 8
#define Nn (Bb*Ll)          // 32768
#define Ee 524288
#define NRr (Nn*Rr)         // 98304

typedef __nv_bfloat16 bf16;

// ---------------- scratch (device globals; no allocations allowed) ----------
__device__ float g_lm[Nn*Dd];
__device__ bf16  g_lmh[Nn*Dd], g_lml[Nn*Dd];
__device__ float g_x[Nn*Dd];
__device__ bf16  g_xh[Nn*Dd], g_xl[Nn*Dd];
__device__ float g_x2[Nn*Dd];
__device__ bf16  g_aggh[(size_t)Nn*Rr*Dd], g_aggl[(size_t)Nn*Rr*Dd];
__device__ bf16  g_Wth[LMD*Dd], g_Wtl[LMD*Dd];
__device__ bf16  g_Wrelh[NLAYERS*Rr*Dd*Dd], g_Wrell[NLAYERS*Rr*Dd*Dd];
__device__ bf16  g_Wrooth[NLAYERS*Dd*Dd], g_Wrootl[NLAYERS*Dd*Dd];
__device__ float g_logits_scratch[Nn*Cc];
__device__ int   g_cnt[NRr];
__device__ int   g_cursor[NRr];
__device__ int   g_off[NRr+1];
__device__ int   g_bsum[128];
__device__ int   g_srcs[Ee];
__device__ float g_loss[2];
__device__ int   g_is64;

// ---------------- small helpers ----------------
__device__ __forceinline__ uint32_t sptr(const void* p) {
    return (uint32_t)__cvta_generic_to_shared(p);
}
__device__ __forceinline__ void bfsplit(float v, bf16& h, bf16& l) {
    h = __float2bfloat16(v);
    l = __float2bfloat16(v - __bfloat162float(h));
}
__device__ __forceinline__ void cpasync16(uint32_t dst, const void* src) {
    asm volatile("cp.async.cg.shared.global [%0], [%1], 16;" :: "r"(dst), "l"(src));
}
#define CP_COMMIT() asm volatile("cp.async.commit_group;")
#define CP_WAIT0()  asm volatile("cp.async.wait_group 0;")

__device__ __forceinline__ void ldsm4(uint32_t& r0, uint32_t& r1, uint32_t& r2, uint32_t& r3,
                                      uint32_t addr) {
    asm volatile("ldmatrix.sync.aligned.m8n8.x4.shared.b16 {%0,%1,%2,%3}, [%4];"
                 : "=r"(r0), "=r"(r1), "=r"(r2), "=r"(r3) : "r"(addr));
}
__device__ __forceinline__ void ldsm4t(uint32_t& r0, uint32_t& r1, uint32_t& r2, uint32_t& r3,
                                       uint32_t addr) {
    asm volatile("ldmatrix.sync.aligned.m8n8.x4.trans.shared.b16 {%0,%1,%2,%3}, [%4];"
                 : "=r"(r0), "=r"(r1), "=r"(r2), "=r"(r3) : "r"(addr));
}
__device__ __forceinline__ void mma16816(float* c, const uint32_t* a, uint32_t b0, uint32_t b1) {
    asm volatile("mma.sync.aligned.m16n8k16.row.col.f32.bf16.bf16.f32 "
                 "{%0,%1,%2,%3},{%4,%5,%6,%7},{%8,%9},{%0,%1,%2,%3};"
                 : "+f"(c[0]), "+f"(c[1]), "+f"(c[2]), "+f"(c[3])
                 : "r"(a[0]), "r"(a[1]), "r"(a[2]), "r"(a[3]), "r"(b0), "r"(b1));
}

// ---------------- int dtype probe ----------------
__global__ void probe_k(const int* __restrict__ p) {
    __shared__ int bad;
    if (threadIdx.x == 0) bad = 0;
    __syncthreads();
    for (int i = threadIdx.x; i < 1024; i += blockDim.x)
        if (p[2*i + 1] != 0) bad = 1;
    __syncthreads();
    if (threadIdx.x == 0) g_is64 = bad ? 0 : 1;
}
__device__ __forceinline__ int load_int(const void* p, long long idx) {
    if (g_is64) return (int)((const long long*)p)[idx];
    return ((const int*)p)[idx];
}

// ---------------- merged setup ----------------
__global__ void setup_k(const float* __restrict__ lm_W,
                        const float* __restrict__ W_rel,
                        const float* __restrict__ W_root) {
    int i = blockIdx.x*blockDim.x + threadIdx.x;
    int stride = gridDim.x*blockDim.x;
    for (; i < LMD*Dd; i += stride) {
        if (i < NRr) { g_cnt[i] = 0; g_cursor[i] = 0; }
        {
            int k = i >> 7, h = i & 127;
            float v = lm_W[h*LMD + k];
            bf16 hi, lo; bfsplit(v, hi, lo);
            g_Wth[i] = hi; g_Wtl[i] = lo;
        }
        if (i < NLAYERS*Rr*Dd*Dd) {
            bf16 hi, lo; bfsplit(W_rel[i], hi, lo);
            g_Wrelh[i] = hi; g_Wrell[i] = lo;
        }
        if (i < NLAYERS*Dd*Dd) {
            bf16 hi, lo; bfsplit(W_root[i], hi, lo);
            g_Wrooth[i] = hi; g_Wrootl[i] = lo;
        }
        if (i < 2) g_loss[i] = 0.f;
    }
}

// ---------------- tensor-core GEMM, 3xBF16 split, cp.async 2-stage pipeline --
// LN mode (lng != null): fuses LayerNorm over the 128-wide output row into
// the epilogue (relu(acc+bias) -> stats -> normalize -> C + Ch/Cl splits).
#define GEMM_SMEM_BF16 (2*128*40*2 + 2*32*136*2 + 2*32*136*2)               // 55296
#define GEMM_SMEM_F32  (2*128*36*4 + 128*40*2 + 128*40*2 + 2*32*136*2*2)    // 92160

__global__ __launch_bounds__(256, 2)
void gemm3_k(const float* __restrict__ A1f,
             const bf16* __restrict__ A1h, const bf16* __restrict__ A1l, int K1,
             const bf16* __restrict__ B1h, const bf16* __restrict__ B1l,
             const bf16* __restrict__ A2h, const bf16* __restrict__ A2l, int K2,
             const bf16* __restrict__ B2h, const bf16* __restrict__ B2l,
             const float* __restrict__ bias, float* __restrict__ C,
             bf16* __restrict__ Ch, bf16* __restrict__ Cl,
             const float* __restrict__ lng, const float* __restrict__ lnb)
{
    extern __shared__ bf16 smem[];

    const int tid  = threadIdx.x;
    const int wid  = tid >> 5;
    const int lane = tid & 31;
    const int wm   = wid >> 2;
    const int wn   = wid & 3;
    const int m0   = blockIdx.x * 128;
    const int g    = lane >> 2;
    const int q    = lane & 3;

    const int b_row0 = tid >> 4, b_cc = (tid & 15) * 8;

    float acc[4][4][4];
#pragma unroll
    for (int i = 0; i < 4; i++)
#pragma unroll
        for (int j = 0; j < 4; j++)
#pragma unroll
            for (int r = 0; r < 4; r++) acc[i][j][r] = 0.f;

    if (A1f) {
        // ---------------- f32-A mode (LM head) ----------------
        float (*Af32)[128][36] = (float(*)[128][36])(smem);
        bf16  (*Ash)[40]       = (bf16(*)[40])(smem + 2*128*36*2);
        bf16  (*Asl)[40]       = (bf16(*)[40])(smem + 2*128*36*2 + 128*40);
        bf16  (*Bs0)[32][136]  = (bf16(*)[32][136])(smem + 2*128*36*2 + 2*128*40);
        bf16  (*Bs1)[32][136]  = (bf16(*)[32][136])(smem + 2*128*36*2 + 2*128*40 + 2*32*136);

        const int K = K1;
        const int T = K >> 5;
        const int af_row = tid >> 3, af_cc = (tid & 7) * 4;

        {
#pragma unroll
            for (int r = 0; r < 4; r++)
                cpasync16(sptr(&Af32[0][af_row + 32*r][af_cc]),
                          A1f + (size_t)(m0 + af_row + 32*r) * K + af_cc);
            cpasync16(sptr(&Bs0[0][b_row0][b_cc]),      B1h + (size_t)b_row0 * 128 + b_cc);
            cpasync16(sptr(&Bs0[0][b_row0 + 16][b_cc]), B1h + (size_t)(b_row0 + 16) * 128 + b_cc);
            cpasync16(sptr(&Bs1[0][b_row0][b_cc]),      B1l + (size_t)b_row0 * 128 + b_cc);
            cpasync16(sptr(&Bs1[0][b_row0 + 16][b_cc]), B1l + (size_t)(b_row0 + 16) * 128 + b_cc);
            CP_COMMIT();
        }

#pragma unroll 1
        for (int t = 0; t < T; t++) {
            CP_WAIT0();
            __syncthreads();
            const int s = t & 1;
            if (t + 1 < T) {
                const int ns = s ^ 1;
                const int kt = (t + 1) << 5;
#pragma unroll
                for (int r = 0; r < 4; r++)
                    cpasync16(sptr(&Af32[ns][af_row + 32*r][af_cc]),
                              A1f + (size_t)(m0 + af_row + 32*r) * K + kt + af_cc);
                cpasync16(sptr(&Bs0[ns][b_row0][b_cc]),      B1h + (size_t)(kt + b_row0) * 128 + b_cc);
                cpasync16(sptr(&Bs0[ns][b_row0 + 16][b_cc]), B1h + (size_t)(kt + b_row0 + 16) * 128 + b_cc);
                cpasync16(sptr(&Bs1[ns][b_row0][b_cc]),      B1l + (size_t)(kt + b_row0) * 128 + b_cc);
                cpasync16(sptr(&Bs1[ns][b_row0 + 16][b_cc]), B1l + (size_t)(kt + b_row0 + 16) * 128 + b_cc);
                CP_COMMIT();
            }
#pragma unroll
            for (int r = 0; r < 4; r++) {
                int row = af_row + 32*r;
                float4 v = *(float4*)&Af32[s][row][af_cc];
                bf16 h0,h1,h2,h3,l0,l1,l2,l3;
                bfsplit(v.x,h0,l0); bfsplit(v.y,h1,l1); bfsplit(v.z,h2,l2); bfsplit(v.w,h3,l3);
                *(__nv_bfloat162*)&Ash[row][af_cc]     = __halves2bfloat162(h0,h1);
                *(__nv_bfloat162*)&Ash[row][af_cc + 2] = __halves2bfloat162(h2,h3);
                *(__nv_bfloat162*)&Asl[row][af_cc]     = __halves2bfloat162(l0,l1);
                *(__nv_bfloat162*)&Asl[row][af_cc + 2] = __halves2bfloat162(l2,l3);
            }
            __syncthreads();

#pragma unroll
            for (int ks = 0; ks < 32; ks += 16) {
                uint32_t af[4][4];
#pragma unroll
                for (int f = 0; f < 4; f++)
                    ldsm4(af[f][0], af[f][1], af[f][2], af[f][3],
                          sptr(&Ash[wm*64 + 16*f + (lane & 15)][ks + ((lane >> 4) << 3)]));
                uint32_t bh[2][4], bl[2][4];
#pragma unroll
                for (int tt = 0; tt < 2; tt++) {
                    ldsm4t(bh[tt][0], bh[tt][1], bh[tt][2], bh[tt][3],
                           sptr(&Bs0[s][ks + (lane & 15)][wn*32 + 16*tt + ((lane >> 4) << 3)]));
                    ldsm4t(bl[tt][0], bl[tt][1], bl[tt][2], bl[tt][3],
                           sptr(&Bs1[s][ks + (lane & 15)][wn*32 + 16*tt + ((lane >> 4) << 3)]));
                }
#pragma unroll
                for (int mf = 0; mf < 4; mf++)
#pragma unroll
                    for (int nf = 0; nf < 4; nf++) {
                        mma16816(acc[mf][nf], af[mf], bh[nf>>1][(nf&1)*2], bh[nf>>1][(nf&1)*2+1]);
                        mma16816(acc[mf][nf], af[mf], bl[nf>>1][(nf&1)*2], bl[nf>>1][(nf&1)*2+1]);
                    }
#pragma unroll
                for (int f = 0; f < 4; f++)
                    ldsm4(af[f][0], af[f][1], af[f][2], af[f][3],
                          sptr(&Asl[wm*64 + 16*f + (lane & 15)][ks + ((lane >> 4) << 3)]));
#pragma unroll
                for (int mf = 0; mf < 4; mf++)
#pragma unroll
                    for (int nf = 0; nf < 4; nf++)
                        mma16816(acc[mf][nf], af[mf], bh[nf>>1][(nf&1)*2], bh[nf>>1][(nf&1)*2+1]);
            }
        }
    } else {
        // ---------------- pre-split bf16 mode, 4 passes ----------------
        bf16 (*As)[128][40]  = (bf16(*)[128][40])(smem);
        bf16 (*Bs0)[32][136] = (bf16(*)[32][136])(smem + 2*128*40);
        bf16 (*Bs1)[32][136] = (bf16(*)[32][136])(smem + 2*128*40 + 2*32*136);
        const int a_row0 = tid >> 2, a_cc = (tid & 3) * 8;

#pragma unroll 1
        for (int pass = 0; pass < 4; pass++) {
            const bf16* Ap; const bf16* Bp0; const bf16* Bp1; int K;
            if      (pass == 0) { Ap = A1h; Bp0 = B1h; Bp1 = B1l; K = K1; }
            else if (pass == 1) { Ap = A1l; Bp0 = B1h; Bp1 = nullptr; K = K1; }
            else if (pass == 2) { Ap = A2h; Bp0 = B2h; Bp1 = B2l; K = K2; }
            else                { Ap = A2l; Bp0 = B2h; Bp1 = nullptr; K = K2; }
            if (Ap == nullptr || K == 0) continue;
            const bool dual = (Bp1 != nullptr);
            const int T = K >> 5;

            {
                cpasync16(sptr(&As[0][a_row0][a_cc]),      Ap + (size_t)(m0 + a_row0) * K + a_cc);
                cpasync16(sptr(&As[0][a_row0 + 64][a_cc]), Ap + (size_t)(m0 + a_row0 + 64) * K + a_cc);
                cpasync16(sptr(&Bs0[0][b_row0][b_cc]),      Bp0 + (size_t)b_row0 * 128 + b_cc);
                cpasync16(sptr(&Bs0[0][b_row0 + 16][b_cc]), Bp0 + (size_t)(b_row0 + 16) * 128 + b_cc);
                if (dual) {
                    cpasync16(sptr(&Bs1[0][b_row0][b_cc]),      Bp1 + (size_t)b_row0 * 128 + b_cc);
                    cpasync16(sptr(&Bs1[0][b_row0 + 16][b_cc]), Bp1 + (size_t)(b_row0 + 16) * 128 + b_cc);
                }
                CP_COMMIT();
            }

#pragma unroll 1
            for (int t = 0; t < T; t++) {
                CP_WAIT0();
                __syncthreads();
                const int s = t & 1;
                if (t + 1 < T) {
                    const int ns = s ^ 1;
                    const int kt = (t + 1) << 5;
                    cpasync16(sptr(&As[ns][a_row0][a_cc]),      Ap + (size_t)(m0 + a_row0) * K + kt + a_cc);
                    cpasync16(sptr(&As[ns][a_row0 + 64][a_cc]), Ap + (size_t)(m0 + a_row0 + 64) * K + kt + a_cc);
                    cpasync16(sptr(&Bs0[ns][b_row0][b_cc]),      Bp0 + (size_t)(kt + b_row0) * 128 + b_cc);
                    cpasync16(sptr(&Bs0[ns][b_row0 + 16][b_cc]), Bp0 + (size_t)(kt + b_row0 + 16) * 128 + b_cc);
                    if (dual) {
                        cpasync16(sptr(&Bs1[ns][b_row0][b_cc]),      Bp1 + (size_t)(kt + b_row0) * 128 + b_cc);
                        cpasync16(sptr(&Bs1[ns][b_row0 + 16][b_cc]), Bp1 + (size_t)(kt + b_row0 + 16) * 128 + b_cc);
                    }
                    CP_COMMIT();
                }

#pragma unroll
                for (int ks = 0; ks < 32; ks += 16) {
                    uint32_t af[4][4];
#pragma unroll
                    for (int f = 0; f < 4; f++)
                        ldsm4(af[f][0], af[f][1], af[f][2], af[f][3],
                              sptr(&As[s][wm*64 + 16*f + (lane & 15)][ks + ((lane >> 4) << 3)]));
                    uint32_t bh[2][4];
#pragma unroll
                    for (int tt = 0; tt < 2; tt++)
                        ldsm4t(bh[tt][0], bh[tt][1], bh[tt][2], bh[tt][3],
                               sptr(&Bs0[s][ks + (lane & 15)][wn*32 + 16*tt + ((lane >> 4) << 3)]));
#pragma unroll
                    for (int mf = 0; mf < 4; mf++)
#pragma unroll
                        for (int nf = 0; nf < 4; nf++)
                            mma16816(acc[mf][nf], af[mf], bh[nf>>1][(nf&1)*2], bh[nf>>1][(nf&1)*2+1]);
                    if (dual) {
                        uint32_t bl[2][4];
#pragma unroll
                        for (int tt = 0; tt < 2; tt++)
                            ldsm4t(bl[tt][0], bl[tt][1], bl[tt][2], bl[tt][3],
                                   sptr(&Bs1[s][ks + (lane & 15)][wn*32 + 16*tt + ((lane >> 4) << 3)]));
#pragma unroll
                        for (int mf = 0; mf < 4; mf++)
#pragma unroll
                            for (int nf = 0; nf < 4; nf++)
                                mma16816(acc[mf][nf], af[mf], bl[nf>>1][(nf&1)*2], bl[nf>>1][(nf&1)*2+1]);
                    }
                }
            }
            __syncthreads();
        }
    }

    if (lng) {
        // ---- fused relu + LayerNorm epilogue (N=128 = full D per row) ----
        // 1) relu(acc+bias) in place; per-thread partial sum/sumsq for 8 rows
        float s8[8], q8[8];
#pragma unroll
        for (int i = 0; i < 8; i++) { s8[i] = 0.f; q8[i] = 0.f; }
#pragma unroll
        for (int nf = 0; nf < 4; nf++) {
            int col = wn*32 + 8*nf + 2*q;
            float b0 = bias[col], b1 = bias[col + 1];
#pragma unroll
            for (int mf = 0; mf < 4; mf++) {
                float v0 = fmaxf(acc[mf][nf][0] + b0, 0.f);
                float v1 = fmaxf(acc[mf][nf][1] + b1, 0.f);
                float v2 = fmaxf(acc[mf][nf][2] + b0, 0.f);
                float v3 = fmaxf(acc[mf][nf][3] + b1, 0.f);
                acc[mf][nf][0] = v0; acc[mf][nf][1] = v1;
                acc[mf][nf][2] = v2; acc[mf][nf][3] = v3;
                s8[mf*2]   += v0 + v1;       q8[mf*2]   += v0*v0 + v1*v1;
                s8[mf*2+1] += v2 + v3;       q8[mf*2+1] += v2*v2 + v3*v3;
            }
        }
        // 2) reduce across the 4 q-lanes (lane bits 0-1)
#pragma unroll
        for (int i = 0; i < 8; i++) {
            s8[i] += __shfl_xor_sync(0xffffffffu, s8[i], 1);
            s8[i] += __shfl_xor_sync(0xffffffffu, s8[i], 2);
            q8[i] += __shfl_xor_sync(0xffffffffu, q8[i], 1);
            q8[i] += __shfl_xor_sync(0xffffffffu, q8[i], 2);
        }
        // 3) cross-warp (wn) exchange via smem: red[row][0..3]=s, [4..7]=sq
        float* red = (float*)smem;   // 128 rows * 8 floats = 4096 B
        __syncthreads();
        if (q == 0) {
#pragma unroll
            for (int mf = 0; mf < 4; mf++) {
#pragma unroll
                for (int h = 0; h < 2; h++) {
                    int row = wm*64 + 16*mf + g + 8*h;
                    red[row*8 + wn]     = s8[mf*2 + h];
                    red[row*8 + 4 + wn] = q8[mf*2 + h];
                }
            }
        }
        __syncthreads();
        float mu8[8], iv8[8];
#pragma unroll
        for (int mf = 0; mf < 4; mf++) {
#pragma unroll
            for (int h = 0; h < 2; h++) {
                int row = wm*64 + 16*mf + g + 8*h;
                float s  = red[row*8+0] + red[row*8+1] + red[row*8+2] + red[row*8+3];
                float sq = red[row*8+4] + red[row*8+5] + red[row*8+6] + red[row*8+7];
                float mu = s * (1.f/128.f);
                float var = sq * (1.f/128.f) - mu*mu;
                mu8[mf*2+h] = mu;
                iv8[mf*2+h] = rsqrtf(var + 1e-5f);
            }
        }
        // 4) normalize + gamma/beta, write C (f32) + Ch/Cl (bf16 splits)
#pragma unroll
        for (int nf = 0; nf < 4; nf++) {
            int col = wn*32 + 8*nf + 2*q;
            float g0 = lng[col], g1 = lng[col + 1];
            float e0 = lnb[col], e1 = lnb[col + 1];
#pragma unroll
            for (int mf = 0; mf < 4; mf++) {
                int row0 = m0 + wm*64 + 16*mf + g;
                float o0 = (acc[mf][nf][0] - mu8[mf*2])   * iv8[mf*2]   * g0 + e0;
                float o1 = (acc[mf][nf][1] - mu8[mf*2])   * iv8[mf*2]   * g1 + e1;
                float o2 = (acc[mf][nf][2] - mu8[mf*2+1]) * iv8[mf*2+1] * g0 + e0;
                float o3 = (acc[mf][nf][3] - mu8[mf*2+1]) * iv8[mf*2+1] * g1 + e1;
                *(float2*)&C[(size_t)row0 * 128 + col]       = make_float2(o0, o1);
                *(float2*)&C[(size_t)(row0 + 8) * 128 + col] = make_float2(o2, o3);
                bf16 h0,h1,h2,h3,l0,l1,l2,l3;
                bfsplit(o0,h0,l0); bfsplit(o1,h1,l1); bfsplit(o2,h2,l2); bfsplit(o3,h3,l3);
                *(__nv_bfloat162*)&Ch[(size_t)row0*128 + col]     = __halves2bfloat162(h0,h1);
                *(__nv_bfloat162*)&Ch[(size_t)(row0+8)*128 + col] = __halves2bfloat162(h2,h3);
                *(__nv_bfloat162*)&Cl[(size_t)row0*128 + col]     = __halves2bfloat162(l0,l1);
                *(__nv_bfloat162*)&Cl[(size_t)(row0+8)*128 + col] = __halves2bfloat162(l2,l3);
            }
        }
    } else {
        // ---- plain epilogue: +bias, relu, store f32 (+ optional bf16 split) ----
#pragma unroll
        for (int nf = 0; nf < 4; nf++) {
            int col = wn*32 + 8*nf + 2*q;
            float b0 = bias[col], b1 = bias[col + 1];
#pragma unroll
            for (int mf = 0; mf < 4; mf++) {
                int row0 = m0 + wm*64 + 16*mf + g;
                float v0 = fmaxf(acc[mf][nf][0] + b0, 0.f);
                float v1 = fmaxf(acc[mf][nf][1] + b1, 0.f);
                float v2 = fmaxf(acc[mf][nf][2] + b0, 0.f);
                float v3 = fmaxf(acc[mf][nf][3] + b1, 0.f);
                *(float2*)&C[(size_t)row0 * 128 + col]       = make_float2(v0, v1);
                *(float2*)&C[(size_t)(row0 + 8) * 128 + col] = make_float2(v2, v3);
                if (Ch) {
                    bf16 h0,h1,h2,h3,l0,l1,l2,l3;
                    bfsplit(v0,h0,l0); bfsplit(v1,h1,l1); bfsplit(v2,h2,l2); bfsplit(v3,h3,l3);
                    *(__nv_bfloat162*)&Ch[(size_t)row0*128 + col]     = __halves2bfloat162(h0,h1);
                    *(__nv_bfloat162*)&Ch[(size_t)(row0+8)*128 + col] = __halves2bfloat162(h2,h3);
                    *(__nv_bfloat162*)&Cl[(size_t)row0*128 + col]     = __halves2bfloat162(l0,l1);
                    *(__nv_bfloat162*)&Cl[(size_t)(row0+8)*128 + col] = __halves2bfloat162(l2,l3);
                }
            }
        }
    }
}

// ---------------- edge preprocessing ----------------
__global__ void hist_k(const void* __restrict__ ei, const void* __restrict__ et) {
    int i = blockIdx.x*blockDim.x + threadIdx.x;
    int stride = gridDim.x*blockDim.x;
    for (; i < Ee; i += stride) {
        int dst = load_int(ei, (long long)Ee + i);
        int rel = load_int(et, i);
        atomicAdd(&g_cnt[dst * Rr + rel], 1);
    }
}

__global__ void scan1_k() {
    __shared__ int wsum[32];
    int tid = threadIdx.x, lane = tid & 31, wid = tid >> 5;
    int gidx = blockIdx.x * 1024 + tid;
    int v = g_cnt[gidx];
    int x = v;
#pragma unroll
    for (int o = 1; o < 32; o <<= 1) {
        int t = __shfl_up_sync(0xffffffffu, x, o);
        if (lane >= o) x += t;
    }
    if (lane == 31) wsum[wid] = x;
    __syncthreads();
    if (wid == 0) {
        int w = wsum[lane];
#pragma unroll
        for (int o = 1; o < 32; o <<= 1) {
            int t = __shfl_up_sync(0xffffffffu, w, o);
            if (lane >= o) w += t;
        }
        wsum[lane] = w;
    }
    __syncthreads();
    int incl = x + (wid ? wsum[wid-1] : 0);
    g_off[gidx] = incl - v;
    if (tid == 1023) g_bsum[blockIdx.x] = incl;
}

__global__ void scan2_k() {
    __shared__ int wsum[4];
    int tid = threadIdx.x, lane = tid & 31, wid = tid >> 5;
    int v = (tid < 96) ? g_bsum[tid] : 0;
    int x = v;
#pragma unroll
    for (int o = 1; o < 32; o <<= 1) {
        int t = __shfl_up_sync(0xffffffffu, x, o);
        if (lane >= o) x += t;
    }
    if (lane == 31) wsum[wid] = x;
    __syncthreads();
    int pre = 0;
    for (int w = 0; w < wid; w++) pre += wsum[w];
    int incl = x + pre;
    if (tid < 96) g_bsum[tid] = incl - v;
    if (tid == 95) g_off[NRr] = incl;
}

__global__ void scan3_k() {
    int gidx = blockIdx.x * 1024 + threadIdx.x;
    g_off[gidx] += g_bsum[blockIdx.x];
}

__global__ void scatter_k(const void* __restrict__ ei, const void* __restrict__ et) {
    int i = blockIdx.x*blockDim.x + threadIdx.x;
    int stride = gridDim.x*blockDim.x;
    for (; i < Ee; i += stride) {
        int dst = load_int(ei, (long long)Ee + i);
        int rel = load_int(et, i);
        int src = load_int(ei, i);
        int seg = dst * Rr + rel;
        int pos = g_off[seg] + atomicAdd(&g_cursor[seg], 1);
        g_srcs[pos] = src;
    }
}

// ---------------- per-segment mean aggregation (float4 loads) ----------------
__global__ void agg_k(const float* __restrict__ x) {
    int warp = blockIdx.x * (blockDim.x >> 5) + (threadIdx.x >> 5);
    if (warp >= NRr) return;
    int lane = threadIdx.x & 31;
    int beg = g_off[warp], end = g_off[warp + 1];
    float4 a = make_float4(0.f, 0.f, 0.f, 0.f);
    for (int i = beg; i < end; i++) {
        const float4* xr = (const float4*)(x + (size_t)g_srcs[i] * 128);
        float4 v = xr[lane];
        a.x += v.x; a.y += v.y; a.z += v.z; a.w += v.w;
    }
    int c = end - beg;
    float inv = 1.f / (float)(c > 0 ? c : 1);
    int n = warp / Rr, r = warp % Rr;
    size_t base = (size_t)n * (Rr*Dd) + r * Dd + lane * 4;
    bf16 h0,h1,h2,h3,l0,l1,l2,l3;
    bfsplit(a.x*inv,h0,l0); bfsplit(a.y*inv,h1,l1);
    bfsplit(a.z*inv,h2,l2); bfsplit(a.w*inv,h3,l3);
    *(__nv_bfloat162*)&g_aggh[base]   = __halves2bfloat162(h0,h1);
    *(__nv_bfloat162*)&g_aggh[base+2] = __halves2bfloat162(h2,h3);
    *(__nv_bfloat162*)&g_aggl[base]   = __halves2bfloat162(l0,l1);
    *(__nv_bfloat162*)&g_aggl[base+2] = __halves2bfloat162(l2,l3);
}

// ---------------- classifier + masked CE ----------------
__global__ void cls_k(const float* __restrict__ lm, const float* __restrict__ gx,
                      const float* __restrict__ W, const float* __restrict__ cb,
                      const void* __restrict__ labels, const void* __restrict__ amask,
                      float* __restrict__ logits_out)
{
    __shared__ float s_nll[8];
    __shared__ float s_val[8];
    int wid = threadIdx.x >> 5, lane = threadIdx.x & 31;
    int row = blockIdx.x * 8 + wid;

    float4 f0, f1;
    if (lane < 16) {
        const float* p = lm + (size_t)row * 128 + lane * 8;
        f0 = *(const float4*)p; f1 = *(const float4*)(p + 4);
    } else {
        const float* p = gx + (size_t)row * 128 + (lane - 16) * 8;
        f0 = *(const float4*)p; f1 = *(const float4*)(p + 4);
    }
    float acc[8];
    const float4* W4 = (const float4*)W;
#pragma unroll
    for (int c = 0; c < 8; c++) {
        float4 w0 = W4[c*64 + lane*2];
        float4 w1 = W4[c*64 + lane*2 + 1];
        acc[c] = f0.x*w0.x + f0.y*w0.y + f0.z*w0.z + f0.w*w0.w
               + f1.x*w1.x + f1.y*w1.y + f1.z*w1.z + f1.w*w1.w;
    }
#pragma unroll
    for (int c = 0; c < 8; c++)
#pragma unroll
        for (int o = 16; o; o >>= 1)
            acc[c] += __shfl_xor_sync(0xffffffffu, acc[c], o);

    if (lane == 0) {
        float lg[8];
#pragma unroll
        for (int c = 0; c < 8; c++) lg[c] = acc[c] + cb[c];
        float mx = lg[0];
#pragma unroll
        for (int c = 1; c < 8; c++) mx = fmaxf(mx, lg[c]);
        float se = 0.f;
#pragma unroll
        for (int c = 0; c < 8; c++) se += expf(lg[c] - mx);
        float lse = mx + logf(se);
#pragma unroll
        for (int c = 0; c < 8; c++) logits_out[(size_t)row * 8 + c] = lg[c];
        int lab = load_int(labels, row);
        bool valid = (load_int(amask, row) == 1);
        s_nll[wid] = valid ? (lse - lg[lab]) : 0.f;
        s_val[wid] = valid ? 1.f : 0.f;
    }
    __syncthreads();
    if (threadIdx.x == 0) {
        float sn = 0.f, sv = 0.f;
#pragma unroll
        for (int i = 0; i < 8; i++) { sn += s_nll[i]; sv += s_val[i]; }
        atomicAdd(&g_loss[0], sn);
        atomicAdd(&g_loss[1], sv);
    }
}

__global__ void fin_k(float* __restrict__ out) {
    out[0] = g_loss[0] / fmaxf(g_loss[1], 1.f);
}

// ---------------- launch ----------------
extern "C" void kernel_launch(void* const* d_in, const int* in_sizes, int n_in,
                              void* d_out, int out_size)
{
    const float* outp   = (const float*)d_in[0];
    const void*  ei     = d_in[1];
    const void*  et     = d_in[2];
    const void*  amask  = d_in[3];
    const void*  labels = d_in[4];
    const float* lm_W   = (const float*)d_in[5];
    const float* lm_b   = (const float*)d_in[6];
    const float* ln_g   = (const float*)d_in[7];
    const float* ln_b   = (const float*)d_in[8];
    const float* W_rel  = (const float*)d_in[9];
    const float* W_root = (const float*)d_in[10];
    const float* conv_b = (const float*)d_in[11];
    const float* cls_W  = (const float*)d_in[12];
    const float* cls_b  = (const float*)d_in[13];
    float* out = (float*)d_out;

    static bool init_done = false;
    static cudaStream_t s2;
    static cudaEvent_t evFork, evJoin;
    if (!init_done) {
        cudaFuncSetAttribute(gemm3_k, cudaFuncAttributeMaxDynamicSharedMemorySize, GEMM_SMEM_F32);
        cudaStreamCreateWithFlags(&s2, cudaStreamNonBlocking);
        cudaEventCreateWithFlags(&evFork, cudaEventDisableTiming);
        cudaEventCreateWithFlags(&evJoin, cudaEventDisableTiming);
        init_done = true;
    }

    void *p_lm, *p_x, *p_x2, *p_lg;
    void *p_Wth, *p_Wtl, *p_aggh, *p_aggl;
    void *p_lmh, *p_lml, *p_xh, *p_xl;
    void *p_Wrelh, *p_Wrell, *p_Wrooth, *p_Wrootl;
    cudaGetSymbolAddress(&p_lm,  g_lm);
    cudaGetSymbolAddress(&p_x,   g_x);
    cudaGetSymbolAddress(&p_x2,  g_x2);
    cudaGetSymbolAddress(&p_lg,  g_logits_scratch);
    cudaGetSymbolAddress(&p_Wth, g_Wth);
    cudaGetSymbolAddress(&p_Wtl, g_Wtl);
    cudaGetSymbolAddress(&p_aggh, g_aggh);
    cudaGetSymbolAddress(&p_aggl, g_aggl);
    cudaGetSymbolAddress(&p_lmh, g_lmh);
    cudaGetSymbolAddress(&p_lml, g_lml);
    cudaGetSymbolAddress(&p_xh,  g_xh);
    cudaGetSymbolAddress(&p_xl,  g_xl);
    cudaGetSymbolAddress(&p_Wrelh, g_Wrelh);
    cudaGetSymbolAddress(&p_Wrell, g_Wrell);
    cudaGetSymbolAddress(&p_Wrooth, g_Wrooth);
    cudaGetSymbolAddress(&p_Wrootl, g_Wrootl);

    float* lm  = (float*)p_lm;
    float* x1  = (float*)p_x;
    float* x2  = (float*)p_x2;
    bf16*  Wth = (bf16*)p_Wth;  bf16* Wtl = (bf16*)p_Wtl;
    bf16*  aggh = (bf16*)p_aggh; bf16* aggl = (bf16*)p_aggl;
    bf16*  lmh = (bf16*)p_lmh;  bf16* lml = (bf16*)p_lml;
    bf16*  xh  = (bf16*)p_xh;   bf16* xl  = (bf16*)p_xl;
    bf16*  Wrelh = (bf16*)p_Wrelh;   bf16* Wrell = (bf16*)p_Wrell;
    bf16*  Wrooth = (bf16*)p_Wrooth; bf16* Wrootl = (bf16*)p_Wrootl;

    probe_k<<<1, 256>>>((const int*)ei);
    setup_k<<<256, 512>>>(lm_W, W_rel, W_root);

    // fork: edge counting sort on s2, concurrent with LM head GEMM(+fused LN)
    cudaEventRecord(evFork, 0);
    cudaStreamWaitEvent(s2, evFork, 0);
    hist_k<<<512, 256, 0, s2>>>(ei, et);
    scan1_k<<<96, 1024, 0, s2>>>();
    scan2_k<<<1, 128, 0, s2>>>();
    scan3_k<<<96, 1024, 0, s2>>>();
    scatter_k<<<512, 256, 0, s2>>>(ei, et);
    cudaEventRecord(evJoin, s2);

    // LM head GEMM with fused relu+LayerNorm epilogue -> lm + lmh/lml
    gemm3_k<<<Nn/128, 256, GEMM_SMEM_F32>>>(outp, nullptr, nullptr, LMD, Wth, Wtl,
                             nullptr, nullptr, 0, nullptr, nullptr,
                             lm_b, lm, lmh, lml, ln_g, ln_b);

    cudaStreamWaitEvent(0, evJoin, 0);

    // layer 0
    agg_k<<<NRr/8, 256>>>(lm);
    gemm3_k<<<Nn/128, 256, GEMM_SMEM_BF16>>>(nullptr, aggh, aggl, Rr*Dd, Wrelh, Wrell,
                             lmh, lml, Dd, Wrooth, Wrootl,
                             conv_b, x1, xh, xl, nullptr, nullptr);
    // layer 1
    agg_k<<<NRr/8, 256>>>(x1);
    gemm3_k<<<Nn/128, 256, GEMM_SMEM_BF16>>>(nullptr, aggh, aggl, Rr*Dd, Wrelh + Rr*Dd*Dd, Wrell + Rr*Dd*Dd,
                             xh, xl, Dd, Wrooth + Dd*Dd, Wrootl + Dd*Dd,
                             conv_b + Dd, x2, nullptr, nullptr, nullptr, nullptr);

    // classifier + loss
    const int LOGITS = Nn * Cc;
    if (out_size >= LOGITS + 1) {
        cls_k<<<Nn/8, 256>>>(lm, x2, cls_W, cls_b, labels, amask, out + 1);
        fin_k<<<1, 1>>>(out);
    } else if (out_size >= LOGITS) {
        cls_k<<<Nn/8, 256>>>(lm, x2, cls_W, cls_b, labels, amask, out);
    } else {
        cls_k<<<Nn/8, 256>>>(lm, x2, cls_W, cls_b, labels, amask, (float*)p_lg);
        fin_k<<<1, 1>>>(out);
    }
}